// round 12
// baseline (speedup 1.0000x reference)
#include <cuda_runtime.h>
#include <cuda_bf16.h>
#include <cstdint>
#include <math.h>

#define B_  4
#define S_  2048
#define D_  1024
#define H_  16
#define HD_ 64

// ---------------------------------------------------------------------------
// Scratch (__device__ globals: allocation-free rule)
// ---------------------------------------------------------------------------
__device__ __nv_bfloat16 g_Xh[(size_t)B_ * S_ * D_];   // X hi, later attn-out hi
__device__ __nv_bfloat16 g_Xl[(size_t)B_ * S_ * D_];
__device__ __nv_bfloat16 g_Qh[(size_t)B_ * S_ * D_];
__device__ __nv_bfloat16 g_Ql[(size_t)B_ * S_ * D_];
__device__ __nv_bfloat16 g_Kh[(size_t)B_ * S_ * D_];
__device__ __nv_bfloat16 g_Kl[(size_t)B_ * S_ * D_];
__device__ __nv_bfloat16 g_Vh[(size_t)B_ * S_ * D_];
__device__ __nv_bfloat16 g_Vl[(size_t)B_ * S_ * D_];
__device__ __nv_bfloat16 g_Wh[4][(size_t)D_ * D_];
__device__ __nv_bfloat16 g_Wl[4][(size_t)D_ * D_];
__device__ float2 g_tab[(size_t)S_ * (D_ / 2)];

__device__ __forceinline__ uint32_t smem_u32(const void* p) {
    uint32_t a;
    asm("{ .reg .u64 t; cvta.to.shared.u64 t, %1; cvt.u32.u64 %0, t; }" : "=r"(a) : "l"(p));
    return a;
}
__device__ __forceinline__ void cp16(uint32_t s, const void* g) {
    asm volatile("cp.async.cg.shared.global [%0], [%1], 16;" :: "r"(s), "l"(g) : "memory");
}
#define LDSM_X4(r0, r1, r2, r3, a)                                              \
    asm volatile("ldmatrix.sync.aligned.m8n8.x4.shared.b16 {%0,%1,%2,%3}, [%4];" \
        : "=r"(r0), "=r"(r1), "=r"(r2), "=r"(r3) : "r"(a))
#define LDSM_X4T(r0, r1, r2, r3, a)                                                   \
    asm volatile("ldmatrix.sync.aligned.m8n8.x4.trans.shared.b16 {%0,%1,%2,%3}, [%4];" \
        : "=r"(r0), "=r"(r1), "=r"(r2), "=r"(r3) : "r"(a))

__device__ __forceinline__ void mma16816(float* d, const uint32_t* a, const uint32_t* b) {
    asm volatile(
        "mma.sync.aligned.m16n8k16.row.col.f32.bf16.bf16.f32 "
        "{%0,%1,%2,%3}, {%4,%5,%6,%7}, {%8,%9}, {%0,%1,%2,%3};"
        : "+f"(d[0]), "+f"(d[1]), "+f"(d[2]), "+f"(d[3])
        : "r"(a[0]), "r"(a[1]), "r"(a[2]), "r"(a[3]), "r"(b[0]), "r"(b[1]));
}

__device__ __forceinline__ uint32_t pack2(float lo, float hi) {
    uint32_t r;
    asm("cvt.rn.bf16x2.f32 %0, %1, %2;" : "=r"(r) : "f"(hi), "f"(lo));
    return r;
}
__device__ __forceinline__ uint32_t pack2_lo(uint32_t hp, float v0, float v1) {
    float r0 = v0 - __uint_as_float(hp << 16);
    float r1 = v1 - __uint_as_float(hp & 0xffff0000u);
    return pack2(r0, r1);
}

// ---------------------------------------------------------------------------
__global__ void rope_table(float2* __restrict__ tab)
{
    const int idx = blockIdx.x * blockDim.x + threadIdx.x;
    const int p = idx & (D_ / 2 - 1);
    const int s = idx >> 9;
    const float inv = exp2f((float)p * (-13.287712379549449f / (float)(D_ / 2)));
    float sn, c;
    sincosf((float)s * inv, &sn, &c);
    tab[idx] = make_float2(c, sn);
}

__global__ void split_bf16(const float4* __restrict__ src,
                           __nv_bfloat16* __restrict__ hi,
                           __nv_bfloat16* __restrict__ lo)
{
    const int i = blockIdx.x * blockDim.x + threadIdx.x;
    float4 x = src[i];
    uint2 h, l;
    h.x = pack2(x.x, x.y); l.x = pack2(x.x - __uint_as_float(h.x << 16),
                                       x.y - __uint_as_float(h.x & 0xffff0000u));
    h.y = pack2(x.z, x.w); l.y = pack2(x.z - __uint_as_float(h.y << 16),
                                       x.w - __uint_as_float(h.y & 0xffff0000u));
    *(uint2*)&hi[(size_t)i * 4] = h;
    *(uint2*)&lo[(size_t)i * 4] = l;
}

__global__ void split_w4(const float4* __restrict__ w0, const float4* __restrict__ w1,
                         const float4* __restrict__ w2, const float4* __restrict__ w3,
                         __nv_bfloat16* __restrict__ hi, __nv_bfloat16* __restrict__ lo)
{
    const int m = blockIdx.y;
    const float4* src = (m == 0) ? w0 : (m == 1) ? w1 : (m == 2) ? w2 : w3;
    const int i = blockIdx.x * blockDim.x + threadIdx.x;
    const size_t off = (size_t)m * D_ * D_ + (size_t)i * 4;
    float4 x = src[i];
    uint2 h, l;
    h.x = pack2(x.x, x.y); l.x = pack2(x.x - __uint_as_float(h.x << 16),
                                       x.y - __uint_as_float(h.x & 0xffff0000u));
    h.y = pack2(x.z, x.w); l.y = pack2(x.z - __uint_as_float(h.y << 16),
                                       x.w - __uint_as_float(h.y & 0xffff0000u));
    *(uint2*)&hi[off] = h;
    *(uint2*)&lo[off] = l;
}

// ---------------------------------------------------------------------------
// GEMM tiles / pipeline constants (validated R11)
// ---------------------------------------------------------------------------
#define BM 128
#define BN 128
#define BK 32
#define APITCH 40
#define BPITCH 136
#define A_BYTES (BM * APITCH * 2)
#define B_BYTES (BK * BPITCH * 2)
#define STG     (2 * A_BYTES + 2 * B_BYTES)   // 37888
#define NSTAGE  3
#define GEMM_SMEM (NSTAGE * STG)              // 113664

#define GEMM_MAINLOOP(Ah, Al, Bh, Bl)                                                     \
    auto load_stage = [&](int s, int k0) {                                                \
        const uint32_t sbst = sbase + (uint32_t)s * STG;                                  \
        _Pragma("unroll")                                                                 \
        for (int it = 0; it < 2; it++) {                                                  \
            const int idx = it * 256 + t;                                                 \
            const int m   = idx >> 2;                                                     \
            const int ca  = idx & 3;                                                      \
            const size_t ga = (size_t)(row0 + m) * 1024 + k0 + ca * 8;                    \
            const uint32_t soa = (uint32_t)(m * APITCH * 2 + ca * 16);                    \
            cp16(sbst + soa,           Ah + ga);                                          \
            cp16(sbst + A_BYTES + soa, Al + ga);                                          \
            const int kr = idx >> 4;                                                      \
            const int cb = idx & 15;                                                      \
            const size_t gb = (size_t)(k0 + kr) * 1024 + col0 + cb * 8;                   \
            const uint32_t sob = (uint32_t)(kr * BPITCH * 2 + cb * 16);                   \
            cp16(sbst + 2 * A_BYTES + sob,           Bh + gb);                            \
            cp16(sbst + 2 * A_BYTES + B_BYTES + sob, Bl + gb);                            \
        }                                                                                 \
        asm volatile("cp.async.commit_group;" ::: "memory");                              \
    };                                                                                    \
    const int NCH = 1024 / BK;                                                            \
    load_stage(0, 0);                                                                     \
    load_stage(1, BK);                                                                    \
    for (int ch = 0; ch < NCH; ch++) {                                                    \
        if (ch + 1 < NCH) asm volatile("cp.async.wait_group 1;" ::: "memory");            \
        else              asm volatile("cp.async.wait_group 0;" ::: "memory");            \
        __syncthreads();                                                                  \
        if (ch + 2 < NCH) load_stage((ch + 2) % NSTAGE, (ch + 2) * BK);                   \
        const uint32_t sb  = sbase + (uint32_t)(ch % NSTAGE) * STG;                       \
        const uint32_t aAh = sb;                                                          \
        const uint32_t aAl = sb + A_BYTES;                                                \
        const uint32_t aBh = sb + 2 * A_BYTES;                                            \
        const uint32_t aBl = aBh + B_BYTES;                                               \
        _Pragma("unroll")                                                                 \
        for (int ks = 0; ks < 2; ks++) {                                                  \
            uint32_t bh[4][2], bl[4][2];                                                  \
            const int kr = ks * 16 + (lane & 15);                                         \
            const int nc = wn * 32 + (lane >> 4) * 8;                                     \
            _Pragma("unroll")                                                             \
            for (int jp = 0; jp < 2; jp++) {                                              \
                const uint32_t off = (uint32_t)((kr * BPITCH + nc + jp * 16) * 2);        \
                LDSM_X4T(bh[2*jp][0], bh[2*jp][1], bh[2*jp+1][0], bh[2*jp+1][1], aBh+off);\
                LDSM_X4T(bl[2*jp][0], bl[2*jp][1], bl[2*jp+1][0], bl[2*jp+1][1], aBl+off);\
            }                                                                             \
            uint32_t ah2[2][4], al2[2][4];                                                \
            const int mr = wm * 64 + (lane & 15);                                         \
            const int kc = ks * 16 + (lane >> 4) * 8;                                     \
            {                                                                             \
                const uint32_t off = (uint32_t)((mr * APITCH + kc) * 2);                  \
                LDSM_X4(ah2[0][0], ah2[0][1], ah2[0][2], ah2[0][3], aAh + off);           \
                LDSM_X4(al2[0][0], al2[0][1], al2[0][2], al2[0][3], aAl + off);           \
            }                                                                             \
            _Pragma("unroll")                                                             \
            for (int i = 0; i < 4; i++) {                                                 \
                if (i < 3) {                                                              \
                    const uint32_t off = (uint32_t)(((mr + (i+1)*16) * APITCH + kc) * 2); \
                    LDSM_X4(ah2[(i+1)&1][0], ah2[(i+1)&1][1],                             \
                            ah2[(i+1)&1][2], ah2[(i+1)&1][3], aAh + off);                 \
                    LDSM_X4(al2[(i+1)&1][0], al2[(i+1)&1][1],                             \
                            al2[(i+1)&1][2], al2[(i+1)&1][3], aAl + off);                 \
                }                                                                         \
                _Pragma("unroll")                                                         \
                for (int j = 0; j < 4; j++) {                                             \
                    mma16816(acc[i][j], ah2[i&1], bh[j]);                                 \
                    mma16816(acc[i][j], ah2[i&1], bl[j]);                                 \
                    mma16816(acc[i][j], al2[i&1], bh[j]);                                 \
                }                                                                         \
            }                                                                             \
        }                                                                                 \
    }

// ---------------------------------------------------------------------------
// Fused Q/K/V projection GEMM (validated R11)
// ---------------------------------------------------------------------------
__global__ __launch_bounds__(256)
void gemm_qkv(const __nv_bfloat16* __restrict__ Ah, const __nv_bfloat16* __restrict__ Al,
              const __nv_bfloat16* __restrict__ Whb, const __nv_bfloat16* __restrict__ Wlb,
              const float* __restrict__ bq, const float* __restrict__ bk,
              const float* __restrict__ bv,
              __nv_bfloat16* __restrict__ Qh, __nv_bfloat16* __restrict__ Ql,
              __nv_bfloat16* __restrict__ Kh, __nv_bfloat16* __restrict__ Kl,
              __nv_bfloat16* __restrict__ Vh, __nv_bfloat16* __restrict__ Vl,
              const float2* __restrict__ tab)
{
    extern __shared__ char smraw[];
    const uint32_t sbase = smem_u32(smraw);
    const int t    = threadIdx.x;
    const int lane = t & 31;
    const int wid  = t >> 5;
    const int wm   = wid & 1;
    const int wn   = wid >> 1;
    const int row0 = blockIdx.y * BM;
    const int col0 = blockIdx.x * BN;
    const int z    = blockIdx.z;

    const size_t WSZ = (size_t)D_ * D_;
    const __nv_bfloat16* Bh = Whb + (size_t)z * WSZ;
    const __nv_bfloat16* Bl = Wlb + (size_t)z * WSZ;
    const float* bias = (z == 0) ? bq : (z == 1) ? bk : bv;
    __nv_bfloat16* Oh = (z == 0) ? Qh : (z == 1) ? Kh : Vh;
    __nv_bfloat16* Ol = (z == 0) ? Ql : (z == 1) ? Kl : Vl;

    float acc[4][4][4];
    #pragma unroll
    for (int i = 0; i < 4; i++)
        #pragma unroll
        for (int j = 0; j < 4; j++)
            #pragma unroll
            for (int v = 0; v < 4; v++) acc[i][j][v] = 0.f;

    GEMM_MAINLOOP(Ah, Al, Bh, Bl)

    const int gr = lane >> 2;
    const int gc = (lane & 3) * 2;
    const bool do_rope = (z < 2);
    #pragma unroll
    for (int i = 0; i < 4; i++) {
        const int r0g = row0 + wm * 64 + i * 16 + gr;
        const int r1g = r0g + 8;
        #pragma unroll
        for (int j = 0; j < 4; j++) {
            const int c = col0 + wn * 32 + j * 8 + gc;
            const float b0 = bias[c], b1 = bias[c + 1];
            float v00 = acc[i][j][0] + b0, v01 = acc[i][j][1] + b1;
            float v10 = acc[i][j][2] + b0, v11 = acc[i][j][3] + b1;
            if (do_rope) {
                const int p = c >> 1;
                const float2 cs0 = tab[(size_t)(r0g & (S_ - 1)) * (D_ / 2) + p];
                const float2 cs1 = tab[(size_t)(r1g & (S_ - 1)) * (D_ / 2) + p];
                float t0 = v00 * cs0.x - v01 * cs0.y;
                float t1 = v00 * cs0.y + v01 * cs0.x;
                v00 = t0; v01 = t1;
                t0 = v10 * cs1.x - v11 * cs1.y;
                t1 = v10 * cs1.y + v11 * cs1.x;
                v10 = t0; v11 = t1;
            }
            const size_t a0 = (size_t)r0g * D_ + c;
            const size_t a1 = (size_t)r1g * D_ + c;
            const uint32_t h0 = pack2(v00, v01);
            const uint32_t h1 = pack2(v10, v11);
            *(uint32_t*)&Oh[a0] = h0;
            *(uint32_t*)&Ol[a0] = pack2_lo(h0, v00, v01);
            *(uint32_t*)&Oh[a1] = h1;
            *(uint32_t*)&Ol[a1] = pack2_lo(h1, v10, v11);
        }
    }
}

// ---------------------------------------------------------------------------
// Output projection GEMM (fp32 epilogue)
// ---------------------------------------------------------------------------
__global__ __launch_bounds__(256)
void gemm_out(const __nv_bfloat16* __restrict__ Ah, const __nv_bfloat16* __restrict__ Al,
              const __nv_bfloat16* __restrict__ Bh, const __nv_bfloat16* __restrict__ Bl,
              const float* __restrict__ bias, float* __restrict__ C)
{
    extern __shared__ char smraw[];
    const uint32_t sbase = smem_u32(smraw);
    const int t    = threadIdx.x;
    const int lane = t & 31;
    const int wid  = t >> 5;
    const int wm   = wid & 1;
    const int wn   = wid >> 1;
    const int row0 = blockIdx.y * BM;
    const int col0 = blockIdx.x * BN;

    float acc[4][4][4];
    #pragma unroll
    for (int i = 0; i < 4; i++)
        #pragma unroll
        for (int j = 0; j < 4; j++)
            #pragma unroll
            for (int v = 0; v < 4; v++) acc[i][j][v] = 0.f;

    GEMM_MAINLOOP(Ah, Al, Bh, Bl)

    const int gr = lane >> 2;
    const int gc = (lane & 3) * 2;
    #pragma unroll
    for (int i = 0; i < 4; i++) {
        const int r0g = row0 + wm * 64 + i * 16 + gr;
        const int r1g = r0g + 8;
        #pragma unroll
        for (int j = 0; j < 4; j++) {
            const int c = col0 + wn * 32 + j * 8 + gc;
            const float b0 = bias[c], b1 = bias[c + 1];
            *(float2*)&C[(size_t)r0g * D_ + c] =
                make_float2(acc[i][j][0] + b0, acc[i][j][1] + b1);
            *(float2*)&C[(size_t)r1g * D_ + c] =
                make_float2(acc[i][j][2] + b0, acc[i][j][3] + b1);
        }
    }
}

// ---------------------------------------------------------------------------
// Tensor-core causal flash attention, bf16x3.
// Q-tile 128 rows, 8 warps (256 thr), KV tile 64 tokens 2-stage.
// Q kept in dedicated smem; fragments re-LDSM'd per kv-tile (regs <= 128).
// ---------------------------------------------------------------------------
#define KROW_B  144                    // 64 bf16 + pad, bytes per row
#define TILE_B  (64 * KROW_B)          // 9216
#define ASTG    (4 * TILE_B)           // Kh,Kl,Vh,Vl per stage = 36864
#define QTILE_B (128 * KROW_B)         // 18432 per Q array
#define ATTN_SMEM (2 * ASTG + 2 * QTILE_B)   // 110592

__global__ __launch_bounds__(256, 2)
void attn_mma(const __nv_bfloat16* __restrict__ Qh, const __nv_bfloat16* __restrict__ Ql,
              const __nv_bfloat16* __restrict__ Kh, const __nv_bfloat16* __restrict__ Kl,
              const __nv_bfloat16* __restrict__ Vh, const __nv_bfloat16* __restrict__ Vl,
              __nv_bfloat16* __restrict__ Oh, __nv_bfloat16* __restrict__ Ol)
{
    extern __shared__ char smraw[];
    const uint32_t sb0  = smem_u32(smraw);
    const uint32_t qbuf = sb0 + 2 * ASTG;
    const int t = threadIdx.x, lane = t & 31, w = t >> 5;
    const int qb = gridDim.x - 1 - blockIdx.x;   // longest tiles first
    const int h = blockIdx.y, b = blockIdx.z;
    const size_t bh = (size_t)b * S_ * D_ + (size_t)h * HD_;
    const int q0 = qb * 128;

    // ---- Q load into dedicated smem (hi+lo), group 0 ----
    #pragma unroll
    for (int it = 0; it < 4; it++) {
        const int idx = it * 256 + t;            // 0..1023
        const int r = idx >> 3, c = idx & 7;
        const size_t g = bh + (size_t)(q0 + r) * D_ + c * 8;
        const uint32_t so = (uint32_t)(r * KROW_B + c * 16);
        cp16(qbuf + so,           Qh + g);
        cp16(qbuf + QTILE_B + so, Ql + g);
    }
    asm volatile("cp.async.commit_group;" ::: "memory");

    auto load_kv = [&](int kb) {
        const uint32_t sb = sb0 + (uint32_t)(kb & 1) * ASTG;
        #pragma unroll
        for (int it = 0; it < 2; it++) {
            const int idx = it * 256 + t;        // 0..511
            const int r = idx >> 3, c = idx & 7;
            const size_t g = bh + (size_t)(kb * 64 + r) * D_ + c * 8;
            const uint32_t so = (uint32_t)(r * KROW_B + c * 16);
            cp16(sb + so,              Kh + g);
            cp16(sb + TILE_B + so,     Kl + g);
            cp16(sb + 2 * TILE_B + so, Vh + g);
            cp16(sb + 3 * TILE_B + so, Vl + g);
        }
        asm volatile("cp.async.commit_group;" ::: "memory");
    };
    load_kv(0);

    const int gr  = lane >> 2;
    const int gc2 = (lane & 3) * 2;
    const int wrow_min = q0 + w * 16;
    const int row0g = wrow_min + gr;
    const int row1g = row0g + 8;

    float m0 = -1e30f, m1 = -1e30f, l0 = 0.f, l1 = 0.f;
    float oa[8][4];
    #pragma unroll
    for (int nf = 0; nf < 8; nf++)
        #pragma unroll
        for (int v = 0; v < 4; v++) oa[nf][v] = 0.f;

    const int kbmax = 2 * qb + 1;
    for (int kb = 0; kb <= kbmax; kb++) {
        asm volatile("cp.async.wait_group 0;" ::: "memory");
        __syncthreads();
        if (kb < kbmax) load_kv(kb + 1);
        const uint32_t sb = sb0 + (uint32_t)(kb & 1) * ASTG;

        // fully-masked tile for this warp: weights are exactly 0 -> skip
        if (kb * 64 > wrow_min + 15) continue;

        // ---- S = Q K^T (x3 terms), Q frags re-LDSM'd from smem ----
        float sa[8][4];
        #pragma unroll
        for (int nf = 0; nf < 8; nf++)
            #pragma unroll
            for (int v = 0; v < 4; v++) sa[nf][v] = 0.f;

        #pragma unroll
        for (int ks = 0; ks < 4; ks++) {
            uint32_t qh4[4], ql4[4];
            {
                const int mr = w * 16 + (lane & 15);
                const uint32_t off = (uint32_t)(mr * KROW_B + ks * 32 + (lane >> 4) * 16);
                LDSM_X4(qh4[0], qh4[1], qh4[2], qh4[3], qbuf + off);
                LDSM_X4(ql4[0], ql4[1], ql4[2], ql4[3], qbuf + QTILE_B + off);
            }
            uint32_t kbh[8][2], kbl[8][2];
            #pragma unroll
            for (int nf16 = 0; nf16 < 4; nf16++) {
                const uint32_t off = (uint32_t)((nf16 * 16 + (lane & 15)) * KROW_B
                                                + ks * 32 + (lane >> 4) * 16);
                uint32_t r0, r1, r2, r3;
                LDSM_X4(r0, r1, r2, r3, sb + off);
                kbh[2 * nf16][0] = r0; kbh[2 * nf16][1] = r2;
                kbh[2 * nf16 + 1][0] = r1; kbh[2 * nf16 + 1][1] = r3;
                LDSM_X4(r0, r1, r2, r3, sb + TILE_B + off);
                kbl[2 * nf16][0] = r0; kbl[2 * nf16][1] = r2;
                kbl[2 * nf16 + 1][0] = r1; kbl[2 * nf16 + 1][1] = r3;
            }
            #pragma unroll
            for (int nf = 0; nf < 8; nf++) {
                mma16816(sa[nf], qh4, kbh[nf]);
                mma16816(sa[nf], qh4, kbl[nf]);
                mma16816(sa[nf], ql4, kbh[nf]);
            }
        }

        #pragma unroll
        for (int nf = 0; nf < 8; nf++)
            #pragma unroll
            for (int v = 0; v < 4; v++) sa[nf][v] *= 0.125f;

        if (kb * 64 + 63 > wrow_min) {   // diagonal tile for this warp
            #pragma unroll
            for (int nf = 0; nf < 8; nf++) {
                const int col = kb * 64 + nf * 8 + gc2;
                if (col     > row0g) sa[nf][0] = -1e30f;
                if (col + 1 > row0g) sa[nf][1] = -1e30f;
                if (col     > row1g) sa[nf][2] = -1e30f;
                if (col + 1 > row1g) sa[nf][3] = -1e30f;
            }
        }

        // ---- online softmax ----
        float mt0 = sa[0][0], mt1 = sa[0][2];
        #pragma unroll
        for (int nf = 0; nf < 8; nf++) {
            mt0 = fmaxf(mt0, fmaxf(sa[nf][0], sa[nf][1]));
            mt1 = fmaxf(mt1, fmaxf(sa[nf][2], sa[nf][3]));
        }
        mt0 = fmaxf(mt0, __shfl_xor_sync(0xffffffffu, mt0, 1));
        mt0 = fmaxf(mt0, __shfl_xor_sync(0xffffffffu, mt0, 2));
        mt1 = fmaxf(mt1, __shfl_xor_sync(0xffffffffu, mt1, 1));
        mt1 = fmaxf(mt1, __shfl_xor_sync(0xffffffffu, mt1, 2));

        const float mn0 = fmaxf(m0, mt0), mn1 = fmaxf(m1, mt1);
        const float c0 = __expf(m0 - mn0), c1 = __expf(m1 - mn1);
        float s0 = 0.f, s1 = 0.f;
        #pragma unroll
        for (int nf = 0; nf < 8; nf++) {
            sa[nf][0] = __expf(sa[nf][0] - mn0); s0 += sa[nf][0];
            sa[nf][1] = __expf(sa[nf][1] - mn0); s0 += sa[nf][1];
            sa[nf][2] = __expf(sa[nf][2] - mn1); s1 += sa[nf][2];
            sa[nf][3] = __expf(sa[nf][3] - mn1); s1 += sa[nf][3];
        }
        s0 += __shfl_xor_sync(0xffffffffu, s0, 1);
        s0 += __shfl_xor_sync(0xffffffffu, s0, 2);
        s1 += __shfl_xor_sync(0xffffffffu, s1, 1);
        s1 += __shfl_xor_sync(0xffffffffu, s1, 2);
        l0 = l0 * c0 + s0;  l1 = l1 * c1 + s1;
        m0 = mn0;           m1 = mn1;

        #pragma unroll
        for (int nf = 0; nf < 8; nf++) {
            oa[nf][0] *= c0; oa[nf][1] *= c0;
            oa[nf][2] *= c1; oa[nf][3] *= c1;
        }

        // ---- O += P V (x3 terms) ----
        #pragma unroll
        for (int ks = 0; ks < 4; ks++) {
            uint32_t ph[4], pl[4];
            ph[0] = pack2(sa[2 * ks][0],     sa[2 * ks][1]);
            pl[0] = pack2_lo(ph[0], sa[2 * ks][0], sa[2 * ks][1]);
            ph[1] = pack2(sa[2 * ks][2],     sa[2 * ks][3]);
            pl[1] = pack2_lo(ph[1], sa[2 * ks][2], sa[2 * ks][3]);
            ph[2] = pack2(sa[2 * ks + 1][0], sa[2 * ks + 1][1]);
            pl[2] = pack2_lo(ph[2], sa[2 * ks + 1][0], sa[2 * ks + 1][1]);
            ph[3] = pack2(sa[2 * ks + 1][2], sa[2 * ks + 1][3]);
            pl[3] = pack2_lo(ph[3], sa[2 * ks + 1][2], sa[2 * ks + 1][3]);

            uint32_t vbh[8][2], vbl[8][2];
            #pragma unroll
            for (int nf16 = 0; nf16 < 4; nf16++) {
                const uint32_t off = (uint32_t)((ks * 16 + (lane & 15)) * KROW_B
                                                + nf16 * 32 + (lane >> 4) * 16);
                LDSM_X4T(vbh[2 * nf16][0], vbh[2 * nf16][1],
                         vbh[2 * nf16 + 1][0], vbh[2 * nf16 + 1][1], sb + 2 * TILE_B + off);
                LDSM_X4T(vbl[2 * nf16][0], vbl[2 * nf16][1],
                         vbl[2 * nf16 + 1][0], vbl[2 * nf16 + 1][1], sb + 3 * TILE_B + off);
            }
            #pragma unroll
            for (int nf = 0; nf < 8; nf++) {
                mma16816(oa[nf], ph, vbh[nf]);
                mma16816(oa[nf], ph, vbl[nf]);
                mma16816(oa[nf], pl, vbh[nf]);
            }
        }
    }

    // ---- epilogue: normalize, split bf16 hi/lo, store ----
    const float iv0 = 1.f / l0, iv1 = 1.f / l1;
    #pragma unroll
    for (int nf = 0; nf < 8; nf++) {
        const size_t a0 = bh + (size_t)row0g * D_ + nf * 8 + gc2;
        const size_t a1 = a0 + 8 * D_;
        const float o00 = oa[nf][0] * iv0, o01 = oa[nf][1] * iv0;
        const float o10 = oa[nf][2] * iv1, o11 = oa[nf][3] * iv1;
        const uint32_t hp0 = pack2(o00, o01);
        const uint32_t hp1 = pack2(o10, o11);
        *(uint32_t*)&Oh[a0] = hp0;
        *(uint32_t*)&Ol[a0] = pack2_lo(hp0, o00, o01);
        *(uint32_t*)&Oh[a1] = hp1;
        *(uint32_t*)&Ol[a1] = pack2_lo(hp1, o10, o11);
    }
}

// ---------------------------------------------------------------------------
extern "C" void kernel_launch(void* const* d_in, const int* in_sizes, int n_in,
                              void* d_out, int out_size)
{
    const float* X  = (const float*)d_in[0];
    const float* Wq = (const float*)d_in[1];
    const float* bq = (const float*)d_in[2];
    const float* Wk = (const float*)d_in[3];
    const float* bk = (const float*)d_in[4];
    const float* Wv = (const float*)d_in[5];
    const float* bv = (const float*)d_in[6];
    const float* Wo = (const float*)d_in[7];
    const float* bo = (const float*)d_in[8];
    float* out = (float*)d_out;

    __nv_bfloat16 *Xh, *Xl, *Wh, *Wl, *Qh, *Ql, *Khb, *Klb, *Vh, *Vl;
    float2* tab;
    cudaGetSymbolAddress((void**)&Xh,  g_Xh);
    cudaGetSymbolAddress((void**)&Xl,  g_Xl);
    cudaGetSymbolAddress((void**)&Wh,  g_Wh);
    cudaGetSymbolAddress((void**)&Wl,  g_Wl);
    cudaGetSymbolAddress((void**)&Qh,  g_Qh);
    cudaGetSymbolAddress((void**)&Ql,  g_Ql);
    cudaGetSymbolAddress((void**)&Khb, g_Kh);
    cudaGetSymbolAddress((void**)&Klb, g_Kl);
    cudaGetSymbolAddress((void**)&Vh,  g_Vh);
    cudaGetSymbolAddress((void**)&Vl,  g_Vl);
    cudaGetSymbolAddress((void**)&tab, g_tab);
    const size_t WSZ = (size_t)D_ * D_;

    const int M = B_ * S_;
    const int nvec4 = M * D_ / 4;
    const int wvec4 = D_ * D_ / 4;

    split_w4<<<dim3(wvec4 / 256, 4), 256>>>((const float4*)Wq, (const float4*)Wk,
                                            (const float4*)Wv, (const float4*)Wo, Wh, Wl);
    rope_table<<<(S_ * (D_ / 2)) / 256, 256>>>(tab);
    split_bf16<<<nvec4 / 256, 256>>>((const float4*)X, Xh, Xl);

    cudaFuncSetAttribute(gemm_qkv, cudaFuncAttributeMaxDynamicSharedMemorySize, GEMM_SMEM);
    cudaFuncSetAttribute(gemm_out, cudaFuncAttributeMaxDynamicSharedMemorySize, GEMM_SMEM);

    gemm_qkv<<<dim3(D_ / BN, M / BM, 3), 256, GEMM_SMEM>>>(
        Xh, Xl, Wh, Wl, bq, bk, bv, Qh, Ql, Khb, Klb, Vh, Vl, tab);

    cudaFuncSetAttribute(attn_mma, cudaFuncAttributeMaxDynamicSharedMemorySize, ATTN_SMEM);
    attn_mma<<<dim3(S_ / 128, H_, B_), 256, ATTN_SMEM>>>(Qh, Ql, Khb, Klb, Vh, Vl, Xh, Xl);

    gemm_out<<<dim3(D_ / BN, M / BM), 256, GEMM_SMEM>>>(
        Xh, Xl, Wh + 3 * WSZ, Wl + 3 * WSZ, bo, out);
}

// round 13
// speedup vs baseline: 1.0151x; 1.0151x over previous
#include <cuda_runtime.h>
#include <cuda_bf16.h>
#include <cstdint>
#include <math.h>

#define B_  4
#define S_  2048
#define D_  1024
#define H_  16
#define HD_ 64

// ---------------------------------------------------------------------------
// Scratch (__device__ globals: allocation-free rule)
// ---------------------------------------------------------------------------
__device__ __nv_bfloat16 g_Xh[(size_t)B_ * S_ * D_];   // X hi, later attn-out hi
__device__ __nv_bfloat16 g_Xl[(size_t)B_ * S_ * D_];
__device__ __nv_bfloat16 g_Qh[(size_t)B_ * S_ * D_];
__device__ __nv_bfloat16 g_Ql[(size_t)B_ * S_ * D_];
__device__ __nv_bfloat16 g_Kh[(size_t)B_ * S_ * D_];
__device__ __nv_bfloat16 g_Kl[(size_t)B_ * S_ * D_];
__device__ __nv_bfloat16 g_Vh[(size_t)B_ * S_ * D_];
__device__ __nv_bfloat16 g_Vl[(size_t)B_ * S_ * D_];
__device__ __nv_bfloat16 g_Wh[4][(size_t)D_ * D_];
__device__ __nv_bfloat16 g_Wl[4][(size_t)D_ * D_];
__device__ float2 g_tab[(size_t)S_ * (D_ / 2)];

__device__ __forceinline__ uint32_t smem_u32(const void* p) {
    uint32_t a;
    asm("{ .reg .u64 t; cvta.to.shared.u64 t, %1; cvt.u32.u64 %0, t; }" : "=r"(a) : "l"(p));
    return a;
}
__device__ __forceinline__ void cp16(uint32_t s, const void* g) {
    asm volatile("cp.async.cg.shared.global [%0], [%1], 16;" :: "r"(s), "l"(g) : "memory");
}
#define LDSM_X4(r0, r1, r2, r3, a)                                              \
    asm volatile("ldmatrix.sync.aligned.m8n8.x4.shared.b16 {%0,%1,%2,%3}, [%4];" \
        : "=r"(r0), "=r"(r1), "=r"(r2), "=r"(r3) : "r"(a))
#define LDSM_X4T(r0, r1, r2, r3, a)                                                   \
    asm volatile("ldmatrix.sync.aligned.m8n8.x4.trans.shared.b16 {%0,%1,%2,%3}, [%4];" \
        : "=r"(r0), "=r"(r1), "=r"(r2), "=r"(r3) : "r"(a))

__device__ __forceinline__ void mma16816(float* d, const uint32_t* a, const uint32_t* b) {
    asm volatile(
        "mma.sync.aligned.m16n8k16.row.col.f32.bf16.bf16.f32 "
        "{%0,%1,%2,%3}, {%4,%5,%6,%7}, {%8,%9}, {%0,%1,%2,%3};"
        : "+f"(d[0]), "+f"(d[1]), "+f"(d[2]), "+f"(d[3])
        : "r"(a[0]), "r"(a[1]), "r"(a[2]), "r"(a[3]), "r"(b[0]), "r"(b[1]));
}

__device__ __forceinline__ uint32_t pack2(float lo, float hi) {
    uint32_t r;
    asm("cvt.rn.bf16x2.f32 %0, %1, %2;" : "=r"(r) : "f"(hi), "f"(lo));
    return r;
}
__device__ __forceinline__ uint32_t pack2_lo(uint32_t hp, float v0, float v1) {
    float r0 = v0 - __uint_as_float(hp << 16);
    float r1 = v1 - __uint_as_float(hp & 0xffff0000u);
    return pack2(r0, r1);
}

// ---------------------------------------------------------------------------
__global__ void rope_table(float2* __restrict__ tab)
{
    const int idx = blockIdx.x * blockDim.x + threadIdx.x;
    const int p = idx & (D_ / 2 - 1);
    const int s = idx >> 9;
    const float inv = exp2f((float)p * (-13.287712379549449f / (float)(D_ / 2)));
    float sn, c;
    sincosf((float)s * inv, &sn, &c);
    tab[idx] = make_float2(c, sn);
}

__global__ void split_bf16(const float4* __restrict__ src,
                           __nv_bfloat16* __restrict__ hi,
                           __nv_bfloat16* __restrict__ lo)
{
    const int i = blockIdx.x * blockDim.x + threadIdx.x;
    float4 x = src[i];
    uint2 h, l;
    h.x = pack2(x.x, x.y); l.x = pack2(x.x - __uint_as_float(h.x << 16),
                                       x.y - __uint_as_float(h.x & 0xffff0000u));
    h.y = pack2(x.z, x.w); l.y = pack2(x.z - __uint_as_float(h.y << 16),
                                       x.w - __uint_as_float(h.y & 0xffff0000u));
    *(uint2*)&hi[(size_t)i * 4] = h;
    *(uint2*)&lo[(size_t)i * 4] = l;
}

__global__ void split_w4(const float4* __restrict__ w0, const float4* __restrict__ w1,
                         const float4* __restrict__ w2, const float4* __restrict__ w3,
                         __nv_bfloat16* __restrict__ hi, __nv_bfloat16* __restrict__ lo)
{
    const int m = blockIdx.y;
    const float4* src = (m == 0) ? w0 : (m == 1) ? w1 : (m == 2) ? w2 : w3;
    const int i = blockIdx.x * blockDim.x + threadIdx.x;
    const size_t off = (size_t)m * D_ * D_ + (size_t)i * 4;
    float4 x = src[i];
    uint2 h, l;
    h.x = pack2(x.x, x.y); l.x = pack2(x.x - __uint_as_float(h.x << 16),
                                       x.y - __uint_as_float(h.x & 0xffff0000u));
    h.y = pack2(x.z, x.w); l.y = pack2(x.z - __uint_as_float(h.y << 16),
                                       x.w - __uint_as_float(h.y & 0xffff0000u));
    *(uint2*)&hi[off] = h;
    *(uint2*)&lo[off] = l;
}

// ---------------------------------------------------------------------------
// GEMM tiles / pipeline constants
// ---------------------------------------------------------------------------
#define BM 128
#define BN 128
#define BK 32
#define APITCH 40
#define BPITCH 136
#define A_BYTES (BM * APITCH * 2)
#define B_BYTES (BK * BPITCH * 2)
#define STG     (2 * A_BYTES + 2 * B_BYTES)   // 37888
#define NSTAGE  3
#define GEMM_SMEM (NSTAGE * STG)              // 113664

// Term-major MMA ordering: 4 independent accumulator chains between
// dependent HMMAs on the same acc (same per-acc FP order -> bit-identical).
#define GEMM_MAINLOOP(Ah, Al, Bh, Bl)                                                     \
    auto load_stage = [&](int s, int k0) {                                                \
        const uint32_t sbst = sbase + (uint32_t)s * STG;                                  \
        _Pragma("unroll")                                                                 \
        for (int it = 0; it < 2; it++) {                                                  \
            const int idx = it * 256 + t;                                                 \
            const int m   = idx >> 2;                                                     \
            const int ca  = idx & 3;                                                      \
            const size_t ga = (size_t)(row0 + m) * 1024 + k0 + ca * 8;                    \
            const uint32_t soa = (uint32_t)(m * APITCH * 2 + ca * 16);                    \
            cp16(sbst + soa,           Ah + ga);                                          \
            cp16(sbst + A_BYTES + soa, Al + ga);                                          \
            const int kr = idx >> 4;                                                      \
            const int cb = idx & 15;                                                      \
            const size_t gb = (size_t)(k0 + kr) * 1024 + col0 + cb * 8;                   \
            const uint32_t sob = (uint32_t)(kr * BPITCH * 2 + cb * 16);                   \
            cp16(sbst + 2 * A_BYTES + sob,           Bh + gb);                            \
            cp16(sbst + 2 * A_BYTES + B_BYTES + sob, Bl + gb);                            \
        }                                                                                 \
        asm volatile("cp.async.commit_group;" ::: "memory");                              \
    };                                                                                    \
    const int NCH = 1024 / BK;                                                            \
    load_stage(0, 0);                                                                     \
    load_stage(1, BK);                                                                    \
    for (int ch = 0; ch < NCH; ch++) {                                                    \
        if (ch + 1 < NCH) asm volatile("cp.async.wait_group 1;" ::: "memory");            \
        else              asm volatile("cp.async.wait_group 0;" ::: "memory");            \
        __syncthreads();                                                                  \
        if (ch + 2 < NCH) load_stage((ch + 2) % NSTAGE, (ch + 2) * BK);                   \
        const uint32_t sb  = sbase + (uint32_t)(ch % NSTAGE) * STG;                       \
        const uint32_t aAh = sb;                                                          \
        const uint32_t aAl = sb + A_BYTES;                                                \
        const uint32_t aBh = sb + 2 * A_BYTES;                                            \
        const uint32_t aBl = aBh + B_BYTES;                                               \
        _Pragma("unroll")                                                                 \
        for (int ks = 0; ks < 2; ks++) {                                                  \
            uint32_t bh[4][2], bl[4][2];                                                  \
            const int kr = ks * 16 + (lane & 15);                                         \
            const int nc = wn * 32 + (lane >> 4) * 8;                                     \
            _Pragma("unroll")                                                             \
            for (int jp = 0; jp < 2; jp++) {                                              \
                const uint32_t off = (uint32_t)((kr * BPITCH + nc + jp * 16) * 2);        \
                LDSM_X4T(bh[2*jp][0], bh[2*jp][1], bh[2*jp+1][0], bh[2*jp+1][1], aBh+off);\
                LDSM_X4T(bl[2*jp][0], bl[2*jp][1], bl[2*jp+1][0], bl[2*jp+1][1], aBl+off);\
            }                                                                             \
            uint32_t ah2[2][4], al2[2][4];                                                \
            const int mr = wm * 64 + (lane & 15);                                         \
            const int kc = ks * 16 + (lane >> 4) * 8;                                     \
            {                                                                             \
                const uint32_t off = (uint32_t)((mr * APITCH + kc) * 2);                  \
                LDSM_X4(ah2[0][0], ah2[0][1], ah2[0][2], ah2[0][3], aAh + off);           \
                LDSM_X4(al2[0][0], al2[0][1], al2[0][2], al2[0][3], aAl + off);           \
            }                                                                             \
            _Pragma("unroll")                                                             \
            for (int i = 0; i < 4; i++) {                                                 \
                if (i < 3) {                                                              \
                    const uint32_t off = (uint32_t)(((mr + (i+1)*16) * APITCH + kc) * 2); \
                    LDSM_X4(ah2[(i+1)&1][0], ah2[(i+1)&1][1],                             \
                            ah2[(i+1)&1][2], ah2[(i+1)&1][3], aAh + off);                 \
                    LDSM_X4(al2[(i+1)&1][0], al2[(i+1)&1][1],                             \
                            al2[(i+1)&1][2], al2[(i+1)&1][3], aAl + off);                 \
                }                                                                         \
                _Pragma("unroll")                                                         \
                for (int j = 0; j < 4; j++) mma16816(acc[i][j], ah2[i&1], bh[j]);         \
                _Pragma("unroll")                                                         \
                for (int j = 0; j < 4; j++) mma16816(acc[i][j], ah2[i&1], bl[j]);         \
                _Pragma("unroll")                                                         \
                for (int j = 0; j < 4; j++) mma16816(acc[i][j], al2[i&1], bh[j]);         \
            }                                                                             \
        }                                                                                 \
    }

// ---------------------------------------------------------------------------
// Fused Q/K/V projection GEMM
// ---------------------------------------------------------------------------
__global__ __launch_bounds__(256)
void gemm_qkv(const __nv_bfloat16* __restrict__ Ah, const __nv_bfloat16* __restrict__ Al,
              const __nv_bfloat16* __restrict__ Whb, const __nv_bfloat16* __restrict__ Wlb,
              const float* __restrict__ bq, const float* __restrict__ bk,
              const float* __restrict__ bv,
              __nv_bfloat16* __restrict__ Qh, __nv_bfloat16* __restrict__ Ql,
              __nv_bfloat16* __restrict__ Kh, __nv_bfloat16* __restrict__ Kl,
              __nv_bfloat16* __restrict__ Vh, __nv_bfloat16* __restrict__ Vl,
              const float2* __restrict__ tab)
{
    extern __shared__ char smraw[];
    const uint32_t sbase = smem_u32(smraw);
    const int t    = threadIdx.x;
    const int lane = t & 31;
    const int wid  = t >> 5;
    const int wm   = wid & 1;
    const int wn   = wid >> 1;
    const int row0 = blockIdx.y * BM;
    const int col0 = blockIdx.x * BN;
    const int z    = blockIdx.z;

    const size_t WSZ = (size_t)D_ * D_;
    const __nv_bfloat16* Bh = Whb + (size_t)z * WSZ;
    const __nv_bfloat16* Bl = Wlb + (size_t)z * WSZ;
    const float* bias = (z == 0) ? bq : (z == 1) ? bk : bv;
    __nv_bfloat16* Oh = (z == 0) ? Qh : (z == 1) ? Kh : Vh;
    __nv_bfloat16* Ol = (z == 0) ? Ql : (z == 1) ? Kl : Vl;

    float acc[4][4][4];
    #pragma unroll
    for (int i = 0; i < 4; i++)
        #pragma unroll
        for (int j = 0; j < 4; j++)
            #pragma unroll
            for (int v = 0; v < 4; v++) acc[i][j][v] = 0.f;

    GEMM_MAINLOOP(Ah, Al, Bh, Bl)

    const int gr = lane >> 2;
    const int gc = (lane & 3) * 2;
    const bool do_rope = (z < 2);
    #pragma unroll
    for (int i = 0; i < 4; i++) {
        const int r0g = row0 + wm * 64 + i * 16 + gr;
        const int r1g = r0g + 8;
        #pragma unroll
        for (int j = 0; j < 4; j++) {
            const int c = col0 + wn * 32 + j * 8 + gc;
            const float b0 = bias[c], b1 = bias[c + 1];
            float v00 = acc[i][j][0] + b0, v01 = acc[i][j][1] + b1;
            float v10 = acc[i][j][2] + b0, v11 = acc[i][j][3] + b1;
            if (do_rope) {
                const int p = c >> 1;
                const float2 cs0 = tab[(size_t)(r0g & (S_ - 1)) * (D_ / 2) + p];
                const float2 cs1 = tab[(size_t)(r1g & (S_ - 1)) * (D_ / 2) + p];
                float t0 = v00 * cs0.x - v01 * cs0.y;
                float t1 = v00 * cs0.y + v01 * cs0.x;
                v00 = t0; v01 = t1;
                t0 = v10 * cs1.x - v11 * cs1.y;
                t1 = v10 * cs1.y + v11 * cs1.x;
                v10 = t0; v11 = t1;
            }
            const size_t a0 = (size_t)r0g * D_ + c;
            const size_t a1 = (size_t)r1g * D_ + c;
            const uint32_t h0 = pack2(v00, v01);
            const uint32_t h1 = pack2(v10, v11);
            *(uint32_t*)&Oh[a0] = h0;
            *(uint32_t*)&Ol[a0] = pack2_lo(h0, v00, v01);
            *(uint32_t*)&Oh[a1] = h1;
            *(uint32_t*)&Ol[a1] = pack2_lo(h1, v10, v11);
        }
    }
}

// ---------------------------------------------------------------------------
// Output projection GEMM (fp32 epilogue)
// ---------------------------------------------------------------------------
__global__ __launch_bounds__(256)
void gemm_out(const __nv_bfloat16* __restrict__ Ah, const __nv_bfloat16* __restrict__ Al,
              const __nv_bfloat16* __restrict__ Bh, const __nv_bfloat16* __restrict__ Bl,
              const float* __restrict__ bias, float* __restrict__ C)
{
    extern __shared__ char smraw[];
    const uint32_t sbase = smem_u32(smraw);
    const int t    = threadIdx.x;
    const int lane = t & 31;
    const int wid  = t >> 5;
    const int wm   = wid & 1;
    const int wn   = wid >> 1;
    const int row0 = blockIdx.y * BM;
    const int col0 = blockIdx.x * BN;

    float acc[4][4][4];
    #pragma unroll
    for (int i = 0; i < 4; i++)
        #pragma unroll
        for (int j = 0; j < 4; j++)
            #pragma unroll
            for (int v = 0; v < 4; v++) acc[i][j][v] = 0.f;

    GEMM_MAINLOOP(Ah, Al, Bh, Bl)

    const int gr = lane >> 2;
    const int gc = (lane & 3) * 2;
    #pragma unroll
    for (int i = 0; i < 4; i++) {
        const int r0g = row0 + wm * 64 + i * 16 + gr;
        const int r1g = r0g + 8;
        #pragma unroll
        for (int j = 0; j < 4; j++) {
            const int c = col0 + wn * 32 + j * 8 + gc;
            const float b0 = bias[c], b1 = bias[c + 1];
            *(float2*)&C[(size_t)r0g * D_ + c] =
                make_float2(acc[i][j][0] + b0, acc[i][j][1] + b1);
            *(float2*)&C[(size_t)r1g * D_ + c] =
                make_float2(acc[i][j][2] + b0, acc[i][j][3] + b1);
        }
    }
}

// ---------------------------------------------------------------------------
// Tensor-core causal flash attention, bf16x3 (R11 structure: 64-row q-tile,
// 4 warps, Q in registers, 2-stage KV, occ 3). Term-major MMA ordering and
// exp2-domain softmax added.
// ---------------------------------------------------------------------------
#define KROW_B 144
#define TILE_B (64 * KROW_B)
#define ASTG   (4 * TILE_B)
#define ATTN_SMEM (2 * ASTG)

__global__ __launch_bounds__(128, 3)
void attn_mma(const __nv_bfloat16* __restrict__ Qh, const __nv_bfloat16* __restrict__ Ql,
              const __nv_bfloat16* __restrict__ Kh, const __nv_bfloat16* __restrict__ Kl,
              const __nv_bfloat16* __restrict__ Vh, const __nv_bfloat16* __restrict__ Vl,
              __nv_bfloat16* __restrict__ Oh, __nv_bfloat16* __restrict__ Ol)
{
    extern __shared__ char smraw[];
    const uint32_t sb0 = smem_u32(smraw);
    const int t = threadIdx.x, lane = t & 31, w = t >> 5;
    const int qb = gridDim.x - 1 - blockIdx.x;
    const int h = blockIdx.y, b = blockIdx.z;
    const size_t bh = (size_t)b * S_ * D_ + (size_t)h * HD_;
    const int q0 = qb * 64;

    auto load_kv = [&](int kb) {
        const uint32_t sb = sb0 + (uint32_t)(kb & 1) * ASTG;
        #pragma unroll
        for (int it = 0; it < 4; it++) {
            const int idx = it * 128 + t;
            const int r = idx >> 3, c = idx & 7;
            const size_t g = bh + (size_t)(kb * 64 + r) * D_ + c * 8;
            const uint32_t so = (uint32_t)(r * KROW_B + c * 16);
            cp16(sb + so,              Kh + g);
            cp16(sb + TILE_B + so,     Kl + g);
            cp16(sb + 2 * TILE_B + so, Vh + g);
            cp16(sb + 3 * TILE_B + so, Vl + g);
        }
        asm volatile("cp.async.commit_group;" ::: "memory");
    };

    // Q stage into stage-1 buffer; overlap with kv(0) load
    const uint32_t qbuf = sb0 + ASTG;
    #pragma unroll
    for (int it = 0; it < 4; it++) {
        const int idx = it * 128 + t;
        const int r = idx >> 3, c = idx & 7;
        const size_t g = bh + (size_t)(q0 + r) * D_ + c * 8;
        const uint32_t so = (uint32_t)(r * KROW_B + c * 16);
        cp16(qbuf + so,          Qh + g);
        cp16(qbuf + TILE_B + so, Ql + g);
    }
    asm volatile("cp.async.commit_group;" ::: "memory");
    load_kv(0);
    asm volatile("cp.async.wait_group 1;" ::: "memory");   // Q landed
    __syncthreads();

    uint32_t qhf[4][4], qlf[4][4];
    {
        const int mr = w * 16 + (lane & 15);
        #pragma unroll
        for (int ks = 0; ks < 4; ks++) {
            const uint32_t off = (uint32_t)(mr * KROW_B + ks * 32 + (lane >> 4) * 16);
            LDSM_X4(qhf[ks][0], qhf[ks][1], qhf[ks][2], qhf[ks][3], qbuf + off);
            LDSM_X4(qlf[ks][0], qlf[ks][1], qlf[ks][2], qlf[ks][3], qbuf + TILE_B + off);
        }
    }
    __syncthreads();   // all warps done reading qbuf before kv(1) overwrites

    const int gr  = lane >> 2;
    const int gc2 = (lane & 3) * 2;
    const int row0g = q0 + w * 16 + gr;
    const int row1g = row0g + 8;

    // softmax in exp2 domain: scores scaled by 0.125*log2(e)
    const float SC2 = 0.125f * 1.44269504f;

    float m0 = -1e30f, m1 = -1e30f, l0 = 0.f, l1 = 0.f;
    float oa[8][4];
    #pragma unroll
    for (int nf = 0; nf < 8; nf++)
        #pragma unroll
        for (int v = 0; v < 4; v++) oa[nf][v] = 0.f;

    for (int kb = 0; kb <= qb; kb++) {
        asm volatile("cp.async.wait_group 0;" ::: "memory");
        __syncthreads();
        if (kb < qb) load_kv(kb + 1);
        const uint32_t sb = sb0 + (uint32_t)(kb & 1) * ASTG;

        float sa[8][4];
        #pragma unroll
        for (int nf = 0; nf < 8; nf++)
            #pragma unroll
            for (int v = 0; v < 4; v++) sa[nf][v] = 0.f;

        #pragma unroll
        for (int ks = 0; ks < 4; ks++) {
            uint32_t kbh[8][2], kbl[8][2];
            #pragma unroll
            for (int nf16 = 0; nf16 < 4; nf16++) {
                const uint32_t off = (uint32_t)((nf16 * 16 + (lane & 15)) * KROW_B
                                                + ks * 32 + (lane >> 4) * 16);
                uint32_t r0, r1, r2, r3;
                LDSM_X4(r0, r1, r2, r3, sb + off);
                kbh[2 * nf16][0] = r0; kbh[2 * nf16][1] = r2;
                kbh[2 * nf16 + 1][0] = r1; kbh[2 * nf16 + 1][1] = r3;
                LDSM_X4(r0, r1, r2, r3, sb + TILE_B + off);
                kbl[2 * nf16][0] = r0; kbl[2 * nf16][1] = r2;
                kbl[2 * nf16 + 1][0] = r1; kbl[2 * nf16 + 1][1] = r3;
            }
            // term-major: 8 independent chains between dependent MMAs
            #pragma unroll
            for (int nf = 0; nf < 8; nf++) mma16816(sa[nf], qhf[ks], kbh[nf]);
            #pragma unroll
            for (int nf = 0; nf < 8; nf++) mma16816(sa[nf], qhf[ks], kbl[nf]);
            #pragma unroll
            for (int nf = 0; nf < 8; nf++) mma16816(sa[nf], qlf[ks], kbh[nf]);
        }

        #pragma unroll
        for (int nf = 0; nf < 8; nf++)
            #pragma unroll
            for (int v = 0; v < 4; v++) sa[nf][v] *= SC2;

        if (kb == qb) {
            #pragma unroll
            for (int nf = 0; nf < 8; nf++) {
                const int col = kb * 64 + nf * 8 + gc2;
                if (col     > row0g) sa[nf][0] = -1e30f;
                if (col + 1 > row0g) sa[nf][1] = -1e30f;
                if (col     > row1g) sa[nf][2] = -1e30f;
                if (col + 1 > row1g) sa[nf][3] = -1e30f;
            }
        }

        float mt0 = sa[0][0], mt1 = sa[0][2];
        #pragma unroll
        for (int nf = 0; nf < 8; nf++) {
            mt0 = fmaxf(mt0, fmaxf(sa[nf][0], sa[nf][1]));
            mt1 = fmaxf(mt1, fmaxf(sa[nf][2], sa[nf][3]));
        }
        mt0 = fmaxf(mt0, __shfl_xor_sync(0xffffffffu, mt0, 1));
        mt0 = fmaxf(mt0, __shfl_xor_sync(0xffffffffu, mt0, 2));
        mt1 = fmaxf(mt1, __shfl_xor_sync(0xffffffffu, mt1, 1));
        mt1 = fmaxf(mt1, __shfl_xor_sync(0xffffffffu, mt1, 2));

        const float mn0 = fmaxf(m0, mt0), mn1 = fmaxf(m1, mt1);
        const float c0 = exp2f(m0 - mn0), c1 = exp2f(m1 - mn1);
        float s0 = 0.f, s1 = 0.f;
        #pragma unroll
        for (int nf = 0; nf < 8; nf++) {
            sa[nf][0] = exp2f(sa[nf][0] - mn0); s0 += sa[nf][0];
            sa[nf][1] = exp2f(sa[nf][1] - mn0); s0 += sa[nf][1];
            sa[nf][2] = exp2f(sa[nf][2] - mn1); s1 += sa[nf][2];
            sa[nf][3] = exp2f(sa[nf][3] - mn1); s1 += sa[nf][3];
        }
        s0 += __shfl_xor_sync(0xffffffffu, s0, 1);
        s0 += __shfl_xor_sync(0xffffffffu, s0, 2);
        s1 += __shfl_xor_sync(0xffffffffu, s1, 1);
        s1 += __shfl_xor_sync(0xffffffffu, s1, 2);
        l0 = l0 * c0 + s0;  l1 = l1 * c1 + s1;
        m0 = mn0;           m1 = mn1;

        #pragma unroll
        for (int nf = 0; nf < 8; nf++) {
            oa[nf][0] *= c0; oa[nf][1] *= c0;
            oa[nf][2] *= c1; oa[nf][3] *= c1;
        }

        #pragma unroll
        for (int ks = 0; ks < 4; ks++) {
            uint32_t ph[4], pl[4];
            ph[0] = pack2(sa[2 * ks][0],     sa[2 * ks][1]);
            pl[0] = pack2_lo(ph[0], sa[2 * ks][0], sa[2 * ks][1]);
            ph[1] = pack2(sa[2 * ks][2],     sa[2 * ks][3]);
            pl[1] = pack2_lo(ph[1], sa[2 * ks][2], sa[2 * ks][3]);
            ph[2] = pack2(sa[2 * ks + 1][0], sa[2 * ks + 1][1]);
            pl[2] = pack2_lo(ph[2], sa[2 * ks + 1][0], sa[2 * ks + 1][1]);
            ph[3] = pack2(sa[2 * ks + 1][2], sa[2 * ks + 1][3]);
            pl[3] = pack2_lo(ph[3], sa[2 * ks + 1][2], sa[2 * ks + 1][3]);

            uint32_t vbh[8][2], vbl[8][2];
            #pragma unroll
            for (int nf16 = 0; nf16 < 4; nf16++) {
                const uint32_t off = (uint32_t)((ks * 16 + (lane & 15)) * KROW_B
                                                + nf16 * 32 + (lane >> 4) * 16);
                LDSM_X4T(vbh[2 * nf16][0], vbh[2 * nf16][1],
                         vbh[2 * nf16 + 1][0], vbh[2 * nf16 + 1][1], sb + 2 * TILE_B + off);
                LDSM_X4T(vbl[2 * nf16][0], vbl[2 * nf16][1],
                         vbl[2 * nf16 + 1][0], vbl[2 * nf16 + 1][1], sb + 3 * TILE_B + off);
            }
            // term-major
            #pragma unroll
            for (int nf = 0; nf < 8; nf++) mma16816(oa[nf], ph, vbh[nf]);
            #pragma unroll
            for (int nf = 0; nf < 8; nf++) mma16816(oa[nf], ph, vbl[nf]);
            #pragma unroll
            for (int nf = 0; nf < 8; nf++) mma16816(oa[nf], pl, vbh[nf]);
        }
    }

    const float iv0 = 1.f / l0, iv1 = 1.f / l1;
    #pragma unroll
    for (int nf = 0; nf < 8; nf++) {
        const size_t a0 = bh + (size_t)(q0 + w * 16 + gr) * D_ + nf * 8 + gc2;
        const size_t a1 = a0 + 8 * D_;
        const float o00 = oa[nf][0] * iv0, o01 = oa[nf][1] * iv0;
        const float o10 = oa[nf][2] * iv1, o11 = oa[nf][3] * iv1;
        const uint32_t hp0 = pack2(o00, o01);
        const uint32_t hp1 = pack2(o10, o11);
        *(uint32_t*)&Oh[a0] = hp0;
        *(uint32_t*)&Ol[a0] = pack2_lo(hp0, o00, o01);
        *(uint32_t*)&Oh[a1] = hp1;
        *(uint32_t*)&Ol[a1] = pack2_lo(hp1, o10, o11);
    }
}

// ---------------------------------------------------------------------------
extern "C" void kernel_launch(void* const* d_in, const int* in_sizes, int n_in,
                              void* d_out, int out_size)
{
    const float* X  = (const float*)d_in[0];
    const float* Wq = (const float*)d_in[1];
    const float* bq = (const float*)d_in[2];
    const float* Wk = (const float*)d_in[3];
    const float* bk = (const float*)d_in[4];
    const float* Wv = (const float*)d_in[5];
    const float* bv = (const float*)d_in[6];
    const float* Wo = (const float*)d_in[7];
    const float* bo = (const float*)d_in[8];
    float* out = (float*)d_out;

    __nv_bfloat16 *Xh, *Xl, *Wh, *Wl, *Qh, *Ql, *Khb, *Klb, *Vh, *Vl;
    float2* tab;
    cudaGetSymbolAddress((void**)&Xh,  g_Xh);
    cudaGetSymbolAddress((void**)&Xl,  g_Xl);
    cudaGetSymbolAddress((void**)&Wh,  g_Wh);
    cudaGetSymbolAddress((void**)&Wl,  g_Wl);
    cudaGetSymbolAddress((void**)&Qh,  g_Qh);
    cudaGetSymbolAddress((void**)&Ql,  g_Ql);
    cudaGetSymbolAddress((void**)&Khb, g_Kh);
    cudaGetSymbolAddress((void**)&Klb, g_Kl);
    cudaGetSymbolAddress((void**)&Vh,  g_Vh);
    cudaGetSymbolAddress((void**)&Vl,  g_Vl);
    cudaGetSymbolAddress((void**)&tab, g_tab);
    const size_t WSZ = (size_t)D_ * D_;

    const int M = B_ * S_;
    const int nvec4 = M * D_ / 4;
    const int wvec4 = D_ * D_ / 4;

    split_w4<<<dim3(wvec4 / 256, 4), 256>>>((const float4*)Wq, (const float4*)Wk,
                                            (const float4*)Wv, (const float4*)Wo, Wh, Wl);
    rope_table<<<(S_ * (D_ / 2)) / 256, 256>>>(tab);
    split_bf16<<<nvec4 / 256, 256>>>((const float4*)X, Xh, Xl);

    cudaFuncSetAttribute(gemm_qkv, cudaFuncAttributeMaxDynamicSharedMemorySize, GEMM_SMEM);
    cudaFuncSetAttribute(gemm_out, cudaFuncAttributeMaxDynamicSharedMemorySize, GEMM_SMEM);

    gemm_qkv<<<dim3(D_ / BN, M / BM, 3), 256, GEMM_SMEM>>>(
        Xh, Xl, Wh, Wl, bq, bk, bv, Qh, Ql, Khb, Klb, Vh, Vl, tab);

    cudaFuncSetAttribute(attn_mma, cudaFuncAttributeMaxDynamicSharedMemorySize, ATTN_SMEM);
    attn_mma<<<dim3(S_ / 64, H_, B_), 128, ATTN_SMEM>>>(Qh, Ql, Khb, Klb, Vh, Vl, Xh, Xl);

    gemm_out<<<dim3(D_ / BN, M / BM), 256, GEMM_SMEM>>>(
        Xh, Xl, Wh + 3 * WSZ, Wl + 3 * WSZ, bo, out);
}

// round 14
// speedup vs baseline: 1.0830x; 1.0669x over previous
#include <cuda_runtime.h>
#include <cuda_bf16.h>
#include <cstdint>
#include <math.h>

#define B_  4
#define S_  2048
#define D_  1024
#define H_  16
#define HD_ 64

// ---------------------------------------------------------------------------
// Scratch (__device__ globals: allocation-free rule)
// ---------------------------------------------------------------------------
__device__ __nv_bfloat16 g_Xh[(size_t)B_ * S_ * D_];   // X hi, later attn-out hi
__device__ __nv_bfloat16 g_Xl[(size_t)B_ * S_ * D_];
__device__ __nv_bfloat16 g_Qh[(size_t)B_ * S_ * D_];
__device__ __nv_bfloat16 g_Ql[(size_t)B_ * S_ * D_];
__device__ __nv_bfloat16 g_Kh[(size_t)B_ * S_ * D_];
__device__ __nv_bfloat16 g_Kl[(size_t)B_ * S_ * D_];
__device__ __nv_bfloat16 g_Vh[(size_t)B_ * S_ * D_];
__device__ __nv_bfloat16 g_Vl[(size_t)B_ * S_ * D_];
__device__ __nv_bfloat16 g_Wh[4][(size_t)D_ * D_];
__device__ __nv_bfloat16 g_Wl[4][(size_t)D_ * D_];
__device__ float2 g_tab[(size_t)S_ * (D_ / 2)];

__device__ __forceinline__ uint32_t smem_u32(const void* p) {
    uint32_t a;
    asm("{ .reg .u64 t; cvta.to.shared.u64 t, %1; cvt.u32.u64 %0, t; }" : "=r"(a) : "l"(p));
    return a;
}
__device__ __forceinline__ void cp16(uint32_t s, const void* g) {
    asm volatile("cp.async.cg.shared.global [%0], [%1], 16;" :: "r"(s), "l"(g) : "memory");
}
#define LDSM_X4(r0, r1, r2, r3, a)                                              \
    asm volatile("ldmatrix.sync.aligned.m8n8.x4.shared.b16 {%0,%1,%2,%3}, [%4];" \
        : "=r"(r0), "=r"(r1), "=r"(r2), "=r"(r3) : "r"(a))
#define LDSM_X4T(r0, r1, r2, r3, a)                                                   \
    asm volatile("ldmatrix.sync.aligned.m8n8.x4.trans.shared.b16 {%0,%1,%2,%3}, [%4];" \
        : "=r"(r0), "=r"(r1), "=r"(r2), "=r"(r3) : "r"(a))

__device__ __forceinline__ void mma16816(float* d, const uint32_t* a, const uint32_t* b) {
    asm volatile(
        "mma.sync.aligned.m16n8k16.row.col.f32.bf16.bf16.f32 "
        "{%0,%1,%2,%3}, {%4,%5,%6,%7}, {%8,%9}, {%0,%1,%2,%3};"
        : "+f"(d[0]), "+f"(d[1]), "+f"(d[2]), "+f"(d[3])
        : "r"(a[0]), "r"(a[1]), "r"(a[2]), "r"(a[3]), "r"(b[0]), "r"(b[1]));
}

__device__ __forceinline__ uint32_t pack2(float lo, float hi) {
    uint32_t r;
    asm("cvt.rn.bf16x2.f32 %0, %1, %2;" : "=r"(r) : "f"(hi), "f"(lo));
    return r;
}
__device__ __forceinline__ uint32_t pack2_lo(uint32_t hp, float v0, float v1) {
    float r0 = v0 - __uint_as_float(hp << 16);
    float r1 = v1 - __uint_as_float(hp & 0xffff0000u);
    return pack2(r0, r1);
}

// ---------------------------------------------------------------------------
// Merged prep: weight splits (blocks 0..4095), rope table (4096..8191),
// X split (8192..16383). One launch instead of three.
// ---------------------------------------------------------------------------
__global__ void prep_all(const float4* __restrict__ X,
                         const float4* __restrict__ w0, const float4* __restrict__ w1,
                         const float4* __restrict__ w2, const float4* __restrict__ w3,
                         __nv_bfloat16* __restrict__ Xh, __nv_bfloat16* __restrict__ Xl,
                         __nv_bfloat16* __restrict__ Wh, __nv_bfloat16* __restrict__ Wl,
                         float2* __restrict__ tab)
{
    const int bid = blockIdx.x;
    const int tid = threadIdx.x;
    if (bid < 4096) {
        // weight split: matrix m, vec4 index i
        const int m = bid >> 10;
        const int i = ((bid & 1023) << 8) + tid;
        const float4* src = (m == 0) ? w0 : (m == 1) ? w1 : (m == 2) ? w2 : w3;
        const size_t off = (size_t)m * D_ * D_ + (size_t)i * 4;
        float4 x = src[i];
        uint2 h, l;
        h.x = pack2(x.x, x.y); l.x = pack2(x.x - __uint_as_float(h.x << 16),
                                           x.y - __uint_as_float(h.x & 0xffff0000u));
        h.y = pack2(x.z, x.w); l.y = pack2(x.z - __uint_as_float(h.y << 16),
                                           x.w - __uint_as_float(h.y & 0xffff0000u));
        *(uint2*)&Wh[off] = h;
        *(uint2*)&Wl[off] = l;
    } else if (bid < 8192) {
        // rope table
        const int idx = ((bid - 4096) << 8) + tid;
        const int p = idx & (D_ / 2 - 1);
        const int s = idx >> 9;
        const float inv = exp2f((float)p * (-13.287712379549449f / (float)(D_ / 2)));
        float sn, c;
        sincosf((float)s * inv, &sn, &c);
        tab[idx] = make_float2(c, sn);
    } else {
        // X split
        const int i = ((bid - 8192) << 8) + tid;
        float4 x = X[i];
        uint2 h, l;
        h.x = pack2(x.x, x.y); l.x = pack2(x.x - __uint_as_float(h.x << 16),
                                           x.y - __uint_as_float(h.x & 0xffff0000u));
        h.y = pack2(x.z, x.w); l.y = pack2(x.z - __uint_as_float(h.y << 16),
                                           x.w - __uint_as_float(h.y & 0xffff0000u));
        *(uint2*)&Xh[(size_t)i * 4] = h;
        *(uint2*)&Xl[(size_t)i * 4] = l;
    }
}

// ---------------------------------------------------------------------------
// GEMM tiles / pipeline constants
// ---------------------------------------------------------------------------
#define BM 128
#define BN 128
#define BK 32
#define APITCH 40
#define BPITCH 136
#define A_BYTES (BM * APITCH * 2)
#define B_BYTES (BK * BPITCH * 2)
#define STG     (2 * A_BYTES + 2 * B_BYTES)   // 37888
#define NSTAGE  3
#define GEMM_SMEM (NSTAGE * STG)              // 113664

// Mainloop: single sync/chunk; next-stage cp.async issued BETWEEN ks0 and ks1
// so the LDGSTS burst hides under tensor-busy time instead of delaying the
// chunk-head LDSMs.
#define GEMM_MAINLOOP(Ah, Al, Bh, Bl)                                                     \
    auto load_stage = [&](int s, int k0) {                                                \
        const uint32_t sbst = sbase + (uint32_t)s * STG;                                  \
        _Pragma("unroll")                                                                 \
        for (int it = 0; it < 2; it++) {                                                  \
            const int idx = it * 256 + t;                                                 \
            const int m   = idx >> 2;                                                     \
            const int ca  = idx & 3;                                                      \
            const size_t ga = (size_t)(row0 + m) * 1024 + k0 + ca * 8;                    \
            const uint32_t soa = (uint32_t)(m * APITCH * 2 + ca * 16);                    \
            cp16(sbst + soa,           Ah + ga);                                          \
            cp16(sbst + A_BYTES + soa, Al + ga);                                          \
            const int kr = idx >> 4;                                                      \
            const int cb = idx & 15;                                                      \
            const size_t gb = (size_t)(k0 + kr) * 1024 + col0 + cb * 8;                   \
            const uint32_t sob = (uint32_t)(kr * BPITCH * 2 + cb * 16);                   \
            cp16(sbst + 2 * A_BYTES + sob,           Bh + gb);                            \
            cp16(sbst + 2 * A_BYTES + B_BYTES + sob, Bl + gb);                            \
        }                                                                                 \
        asm volatile("cp.async.commit_group;" ::: "memory");                              \
    };                                                                                    \
    const int NCH = 1024 / BK;                                                            \
    load_stage(0, 0);                                                                     \
    load_stage(1, BK);                                                                    \
    for (int ch = 0; ch < NCH; ch++) {                                                    \
        if (ch + 1 < NCH) asm volatile("cp.async.wait_group 1;" ::: "memory");            \
        else              asm volatile("cp.async.wait_group 0;" ::: "memory");            \
        __syncthreads();                                                                  \
        const uint32_t sb  = sbase + (uint32_t)(ch % NSTAGE) * STG;                       \
        const uint32_t aAh = sb;                                                          \
        const uint32_t aAl = sb + A_BYTES;                                                \
        const uint32_t aBh = sb + 2 * A_BYTES;                                            \
        const uint32_t aBl = aBh + B_BYTES;                                               \
        _Pragma("unroll")                                                                 \
        for (int ks = 0; ks < 2; ks++) {                                                  \
            uint32_t bh[4][2], bl[4][2];                                                  \
            const int kr = ks * 16 + (lane & 15);                                         \
            const int nc = wn * 32 + (lane >> 4) * 8;                                     \
            _Pragma("unroll")                                                             \
            for (int jp = 0; jp < 2; jp++) {                                              \
                const uint32_t off = (uint32_t)((kr * BPITCH + nc + jp * 16) * 2);        \
                LDSM_X4T(bh[2*jp][0], bh[2*jp][1], bh[2*jp+1][0], bh[2*jp+1][1], aBh+off);\
                LDSM_X4T(bl[2*jp][0], bl[2*jp][1], bl[2*jp+1][0], bl[2*jp+1][1], aBl+off);\
            }                                                                             \
            uint32_t ah2[2][4], al2[2][4];                                                \
            const int mr = wm * 64 + (lane & 15);                                         \
            const int kc = ks * 16 + (lane >> 4) * 8;                                     \
            {                                                                             \
                const uint32_t off = (uint32_t)((mr * APITCH + kc) * 2);                  \
                LDSM_X4(ah2[0][0], ah2[0][1], ah2[0][2], ah2[0][3], aAh + off);           \
                LDSM_X4(al2[0][0], al2[0][1], al2[0][2], al2[0][3], aAl + off);           \
            }                                                                             \
            _Pragma("unroll")                                                             \
            for (int i = 0; i < 4; i++) {                                                 \
                if (i < 3) {                                                              \
                    const uint32_t off = (uint32_t)(((mr + (i+1)*16) * APITCH + kc) * 2); \
                    LDSM_X4(ah2[(i+1)&1][0], ah2[(i+1)&1][1],                             \
                            ah2[(i+1)&1][2], ah2[(i+1)&1][3], aAh + off);                 \
                    LDSM_X4(al2[(i+1)&1][0], al2[(i+1)&1][1],                             \
                            al2[(i+1)&1][2], al2[(i+1)&1][3], aAl + off);                 \
                }                                                                         \
                _Pragma("unroll")                                                         \
                for (int j = 0; j < 4; j++) mma16816(acc[i][j], ah2[i&1], bh[j]);         \
                _Pragma("unroll")                                                         \
                for (int j = 0; j < 4; j++) mma16816(acc[i][j], ah2[i&1], bl[j]);         \
                _Pragma("unroll")                                                         \
                for (int j = 0; j < 4; j++) mma16816(acc[i][j], al2[i&1], bh[j]);         \
            }                                                                             \
            if (ks == 0 && ch + 2 < NCH) load_stage((ch + 2) % NSTAGE, (ch + 2) * BK);    \
        }                                                                                 \
    }

// ---------------------------------------------------------------------------
// Fused Q/K/V projection GEMM
// ---------------------------------------------------------------------------
__global__ __launch_bounds__(256)
void gemm_qkv(const __nv_bfloat16* __restrict__ Ah, const __nv_bfloat16* __restrict__ Al,
              const __nv_bfloat16* __restrict__ Whb, const __nv_bfloat16* __restrict__ Wlb,
              const float* __restrict__ bq, const float* __restrict__ bk,
              const float* __restrict__ bv,
              __nv_bfloat16* __restrict__ Qh, __nv_bfloat16* __restrict__ Ql,
              __nv_bfloat16* __restrict__ Kh, __nv_bfloat16* __restrict__ Kl,
              __nv_bfloat16* __restrict__ Vh, __nv_bfloat16* __restrict__ Vl,
              const float2* __restrict__ tab)
{
    extern __shared__ char smraw[];
    const uint32_t sbase = smem_u32(smraw);
    const int t    = threadIdx.x;
    const int lane = t & 31;
    const int wid  = t >> 5;
    const int wm   = wid & 1;
    const int wn   = wid >> 1;
    const int row0 = blockIdx.y * BM;
    const int col0 = blockIdx.x * BN;
    const int z    = blockIdx.z;

    const size_t WSZ = (size_t)D_ * D_;
    const __nv_bfloat16* Bh = Whb + (size_t)z * WSZ;
    const __nv_bfloat16* Bl = Wlb + (size_t)z * WSZ;
    const float* bias = (z == 0) ? bq : (z == 1) ? bk : bv;
    __nv_bfloat16* Oh = (z == 0) ? Qh : (z == 1) ? Kh : Vh;
    __nv_bfloat16* Ol = (z == 0) ? Ql : (z == 1) ? Kl : Vl;

    float acc[4][4][4];
    #pragma unroll
    for (int i = 0; i < 4; i++)
        #pragma unroll
        for (int j = 0; j < 4; j++)
            #pragma unroll
            for (int v = 0; v < 4; v++) acc[i][j][v] = 0.f;

    GEMM_MAINLOOP(Ah, Al, Bh, Bl)

    const int gr = lane >> 2;
    const int gc = (lane & 3) * 2;
    const bool do_rope = (z < 2);
    #pragma unroll
    for (int i = 0; i < 4; i++) {
        const int r0g = row0 + wm * 64 + i * 16 + gr;
        const int r1g = r0g + 8;
        #pragma unroll
        for (int j = 0; j < 4; j++) {
            const int c = col0 + wn * 32 + j * 8 + gc;
            const float b0 = bias[c], b1 = bias[c + 1];
            float v00 = acc[i][j][0] + b0, v01 = acc[i][j][1] + b1;
            float v10 = acc[i][j][2] + b0, v11 = acc[i][j][3] + b1;
            if (do_rope) {
                const int p = c >> 1;
                const float2 cs0 = tab[(size_t)(r0g & (S_ - 1)) * (D_ / 2) + p];
                const float2 cs1 = tab[(size_t)(r1g & (S_ - 1)) * (D_ / 2) + p];
                float t0 = v00 * cs0.x - v01 * cs0.y;
                float t1 = v00 * cs0.y + v01 * cs0.x;
                v00 = t0; v01 = t1;
                t0 = v10 * cs1.x - v11 * cs1.y;
                t1 = v10 * cs1.y + v11 * cs1.x;
                v10 = t0; v11 = t1;
            }
            const size_t a0 = (size_t)r0g * D_ + c;
            const size_t a1 = (size_t)r1g * D_ + c;
            const uint32_t h0 = pack2(v00, v01);
            const uint32_t h1 = pack2(v10, v11);
            *(uint32_t*)&Oh[a0] = h0;
            *(uint32_t*)&Ol[a0] = pack2_lo(h0, v00, v01);
            *(uint32_t*)&Oh[a1] = h1;
            *(uint32_t*)&Ol[a1] = pack2_lo(h1, v10, v11);
        }
    }
}

// ---------------------------------------------------------------------------
// Output projection GEMM (fp32 epilogue)
// ---------------------------------------------------------------------------
__global__ __launch_bounds__(256)
void gemm_out(const __nv_bfloat16* __restrict__ Ah, const __nv_bfloat16* __restrict__ Al,
              const __nv_bfloat16* __restrict__ Bh, const __nv_bfloat16* __restrict__ Bl,
              const float* __restrict__ bias, float* __restrict__ C)
{
    extern __shared__ char smraw[];
    const uint32_t sbase = smem_u32(smraw);
    const int t    = threadIdx.x;
    const int lane = t & 31;
    const int wid  = t >> 5;
    const int wm   = wid & 1;
    const int wn   = wid >> 1;
    const int row0 = blockIdx.y * BM;
    const int col0 = blockIdx.x * BN;

    float acc[4][4][4];
    #pragma unroll
    for (int i = 0; i < 4; i++)
        #pragma unroll
        for (int j = 0; j < 4; j++)
            #pragma unroll
            for (int v = 0; v < 4; v++) acc[i][j][v] = 0.f;

    GEMM_MAINLOOP(Ah, Al, Bh, Bl)

    const int gr = lane >> 2;
    const int gc = (lane & 3) * 2;
    #pragma unroll
    for (int i = 0; i < 4; i++) {
        const int r0g = row0 + wm * 64 + i * 16 + gr;
        const int r1g = r0g + 8;
        #pragma unroll
        for (int j = 0; j < 4; j++) {
            const int c = col0 + wn * 32 + j * 8 + gc;
            const float b0 = bias[c], b1 = bias[c + 1];
            *(float2*)&C[(size_t)r0g * D_ + c] =
                make_float2(acc[i][j][0] + b0, acc[i][j][1] + b1);
            *(float2*)&C[(size_t)r1g * D_ + c] =
                make_float2(acc[i][j][2] + b0, acc[i][j][3] + b1);
        }
    }
}

// ---------------------------------------------------------------------------
// Tensor-core causal flash attention, bf16x3 — EXACT R11 version (900.1 µs):
// 64-row q-tile, 4 warps, Q in registers, 2-stage KV, occ 3, single sync.
// ---------------------------------------------------------------------------
#define KROW_B 144
#define TILE_B (64 * KROW_B)
#define ASTG   (4 * TILE_B)
#define ATTN_SMEM (2 * ASTG)

__global__ __launch_bounds__(128, 3)
void attn_mma(const __nv_bfloat16* __restrict__ Qh, const __nv_bfloat16* __restrict__ Ql,
              const __nv_bfloat16* __restrict__ Kh, const __nv_bfloat16* __restrict__ Kl,
              const __nv_bfloat16* __restrict__ Vh, const __nv_bfloat16* __restrict__ Vl,
              __nv_bfloat16* __restrict__ Oh, __nv_bfloat16* __restrict__ Ol)
{
    extern __shared__ char smraw[];
    const uint32_t sb0 = smem_u32(smraw);
    const int t = threadIdx.x, lane = t & 31, w = t >> 5;
    const int qb = gridDim.x - 1 - blockIdx.x;
    const int h = blockIdx.y, b = blockIdx.z;
    const size_t bh = (size_t)b * S_ * D_ + (size_t)h * HD_;
    const int q0 = qb * 64;

    auto load_kv = [&](int kb) {
        const uint32_t sb = sb0 + (uint32_t)(kb & 1) * ASTG;
        #pragma unroll
        for (int it = 0; it < 4; it++) {
            const int idx = it * 128 + t;
            const int r = idx >> 3, c = idx & 7;
            const size_t g = bh + (size_t)(kb * 64 + r) * D_ + c * 8;
            const uint32_t so = (uint32_t)(r * KROW_B + c * 16);
            cp16(sb + so,              Kh + g);
            cp16(sb + TILE_B + so,     Kl + g);
            cp16(sb + 2 * TILE_B + so, Vh + g);
            cp16(sb + 3 * TILE_B + so, Vl + g);
        }
        asm volatile("cp.async.commit_group;" ::: "memory");
    };

    // Q stage into stage-1 buffer; overlap with kv(0) load
    const uint32_t qbuf = sb0 + ASTG;
    #pragma unroll
    for (int it = 0; it < 4; it++) {
        const int idx = it * 128 + t;
        const int r = idx >> 3, c = idx & 7;
        const size_t g = bh + (size_t)(q0 + r) * D_ + c * 8;
        const uint32_t so = (uint32_t)(r * KROW_B + c * 16);
        cp16(qbuf + so,          Qh + g);
        cp16(qbuf + TILE_B + so, Ql + g);
    }
    asm volatile("cp.async.commit_group;" ::: "memory");
    load_kv(0);
    asm volatile("cp.async.wait_group 1;" ::: "memory");   // Q landed
    __syncthreads();

    uint32_t qhf[4][4], qlf[4][4];
    {
        const int mr = w * 16 + (lane & 15);
        #pragma unroll
        for (int ks = 0; ks < 4; ks++) {
            const uint32_t off = (uint32_t)(mr * KROW_B + ks * 32 + (lane >> 4) * 16);
            LDSM_X4(qhf[ks][0], qhf[ks][1], qhf[ks][2], qhf[ks][3], qbuf + off);
            LDSM_X4(qlf[ks][0], qlf[ks][1], qlf[ks][2], qlf[ks][3], qbuf + TILE_B + off);
        }
    }
    __syncthreads();   // all warps done reading qbuf before kv(1) overwrites

    const int gr  = lane >> 2;
    const int gc2 = (lane & 3) * 2;
    const int row0g = q0 + w * 16 + gr;
    const int row1g = row0g + 8;

    float m0 = -1e30f, m1 = -1e30f, l0 = 0.f, l1 = 0.f;
    float oa[8][4];
    #pragma unroll
    for (int nf = 0; nf < 8; nf++)
        #pragma unroll
        for (int v = 0; v < 4; v++) oa[nf][v] = 0.f;

    for (int kb = 0; kb <= qb; kb++) {
        asm volatile("cp.async.wait_group 0;" ::: "memory");
        __syncthreads();
        if (kb < qb) load_kv(kb + 1);
        const uint32_t sb = sb0 + (uint32_t)(kb & 1) * ASTG;

        float sa[8][4];
        #pragma unroll
        for (int nf = 0; nf < 8; nf++)
            #pragma unroll
            for (int v = 0; v < 4; v++) sa[nf][v] = 0.f;

        #pragma unroll
        for (int ks = 0; ks < 4; ks++) {
            uint32_t kbh[8][2], kbl[8][2];
            #pragma unroll
            for (int nf16 = 0; nf16 < 4; nf16++) {
                const uint32_t off = (uint32_t)((nf16 * 16 + (lane & 15)) * KROW_B
                                                + ks * 32 + (lane >> 4) * 16);
                uint32_t r0, r1, r2, r3;
                LDSM_X4(r0, r1, r2, r3, sb + off);
                kbh[2 * nf16][0] = r0; kbh[2 * nf16][1] = r2;
                kbh[2 * nf16 + 1][0] = r1; kbh[2 * nf16 + 1][1] = r3;
                LDSM_X4(r0, r1, r2, r3, sb + TILE_B + off);
                kbl[2 * nf16][0] = r0; kbl[2 * nf16][1] = r2;
                kbl[2 * nf16 + 1][0] = r1; kbl[2 * nf16 + 1][1] = r3;
            }
            #pragma unroll
            for (int nf = 0; nf < 8; nf++) {
                mma16816(sa[nf], qhf[ks], kbh[nf]);
                mma16816(sa[nf], qhf[ks], kbl[nf]);
                mma16816(sa[nf], qlf[ks], kbh[nf]);
            }
        }

        #pragma unroll
        for (int nf = 0; nf < 8; nf++)
            #pragma unroll
            for (int v = 0; v < 4; v++) sa[nf][v] *= 0.125f;

        if (kb == qb) {
            #pragma unroll
            for (int nf = 0; nf < 8; nf++) {
                const int col = kb * 64 + nf * 8 + gc2;
                if (col     > row0g) sa[nf][0] = -1e30f;
                if (col + 1 > row0g) sa[nf][1] = -1e30f;
                if (col     > row1g) sa[nf][2] = -1e30f;
                if (col + 1 > row1g) sa[nf][3] = -1e30f;
            }
        }

        float mt0 = sa[0][0], mt1 = sa[0][2];
        #pragma unroll
        for (int nf = 0; nf < 8; nf++) {
            mt0 = fmaxf(mt0, fmaxf(sa[nf][0], sa[nf][1]));
            mt1 = fmaxf(mt1, fmaxf(sa[nf][2], sa[nf][3]));
        }
        mt0 = fmaxf(mt0, __shfl_xor_sync(0xffffffffu, mt0, 1));
        mt0 = fmaxf(mt0, __shfl_xor_sync(0xffffffffu, mt0, 2));
        mt1 = fmaxf(mt1, __shfl_xor_sync(0xffffffffu, mt1, 1));
        mt1 = fmaxf(mt1, __shfl_xor_sync(0xffffffffu, mt1, 2));

        const float mn0 = fmaxf(m0, mt0), mn1 = fmaxf(m1, mt1);
        const float c0 = __expf(m0 - mn0), c1 = __expf(m1 - mn1);
        float s0 = 0.f, s1 = 0.f;
        #pragma unroll
        for (int nf = 0; nf < 8; nf++) {
            sa[nf][0] = __expf(sa[nf][0] - mn0); s0 += sa[nf][0];
            sa[nf][1] = __expf(sa[nf][1] - mn0); s0 += sa[nf][1];
            sa[nf][2] = __expf(sa[nf][2] - mn1); s1 += sa[nf][2];
            sa[nf][3] = __expf(sa[nf][3] - mn1); s1 += sa[nf][3];
        }
        s0 += __shfl_xor_sync(0xffffffffu, s0, 1);
        s0 += __shfl_xor_sync(0xffffffffu, s0, 2);
        s1 += __shfl_xor_sync(0xffffffffu, s1, 1);
        s1 += __shfl_xor_sync(0xffffffffu, s1, 2);
        l0 = l0 * c0 + s0;  l1 = l1 * c1 + s1;
        m0 = mn0;           m1 = mn1;

        #pragma unroll
        for (int nf = 0; nf < 8; nf++) {
            oa[nf][0] *= c0; oa[nf][1] *= c0;
            oa[nf][2] *= c1; oa[nf][3] *= c1;
        }

        #pragma unroll
        for (int ks = 0; ks < 4; ks++) {
            uint32_t ph[4], pl[4];
            ph[0] = pack2(sa[2 * ks][0],     sa[2 * ks][1]);
            pl[0] = pack2_lo(ph[0], sa[2 * ks][0], sa[2 * ks][1]);
            ph[1] = pack2(sa[2 * ks][2],     sa[2 * ks][3]);
            pl[1] = pack2_lo(ph[1], sa[2 * ks][2], sa[2 * ks][3]);
            ph[2] = pack2(sa[2 * ks + 1][0], sa[2 * ks + 1][1]);
            pl[2] = pack2_lo(ph[2], sa[2 * ks + 1][0], sa[2 * ks + 1][1]);
            ph[3] = pack2(sa[2 * ks + 1][2], sa[2 * ks + 1][3]);
            pl[3] = pack2_lo(ph[3], sa[2 * ks + 1][2], sa[2 * ks + 1][3]);

            uint32_t vbh[8][2], vbl[8][2];
            #pragma unroll
            for (int nf16 = 0; nf16 < 4; nf16++) {
                const uint32_t off = (uint32_t)((ks * 16 + (lane & 15)) * KROW_B
                                                + nf16 * 32 + (lane >> 4) * 16);
                LDSM_X4T(vbh[2 * nf16][0], vbh[2 * nf16][1],
                         vbh[2 * nf16 + 1][0], vbh[2 * nf16 + 1][1], sb + 2 * TILE_B + off);
                LDSM_X4T(vbl[2 * nf16][0], vbl[2 * nf16][1],
                         vbl[2 * nf16 + 1][0], vbl[2 * nf16 + 1][1], sb + 3 * TILE_B + off);
            }
            #pragma unroll
            for (int nf = 0; nf < 8; nf++) {
                mma16816(oa[nf], ph, vbh[nf]);
                mma16816(oa[nf], ph, vbl[nf]);
                mma16816(oa[nf], pl, vbh[nf]);
            }
        }
    }

    const float iv0 = 1.f / l0, iv1 = 1.f / l1;
    #pragma unroll
    for (int nf = 0; nf < 8; nf++) {
        const size_t a0 = bh + (size_t)(q0 + w * 16 + gr) * D_ + nf * 8 + gc2;
        const size_t a1 = a0 + 8 * D_;
        const float o00 = oa[nf][0] * iv0, o01 = oa[nf][1] * iv0;
        const float o10 = oa[nf][2] * iv1, o11 = oa[nf][3] * iv1;
        const uint32_t hp0 = pack2(o00, o01);
        const uint32_t hp1 = pack2(o10, o11);
        *(uint32_t*)&Oh[a0] = hp0;
        *(uint32_t*)&Ol[a0] = pack2_lo(hp0, o00, o01);
        *(uint32_t*)&Oh[a1] = hp1;
        *(uint32_t*)&Ol[a1] = pack2_lo(hp1, o10, o11);
    }
}

// ---------------------------------------------------------------------------
extern "C" void kernel_launch(void* const* d_in, const int* in_sizes, int n_in,
                              void* d_out, int out_size)
{
    const float* X  = (const float*)d_in[0];
    const float* Wq = (const float*)d_in[1];
    const float* bq = (const float*)d_in[2];
    const float* Wk = (const float*)d_in[3];
    const float* bk = (const float*)d_in[4];
    const float* Wv = (const float*)d_in[5];
    const float* bv = (const float*)d_in[6];
    const float* Wo = (const float*)d_in[7];
    const float* bo = (const float*)d_in[8];
    float* out = (float*)d_out;

    __nv_bfloat16 *Xh, *Xl, *Wh, *Wl, *Qh, *Ql, *Khb, *Klb, *Vh, *Vl;
    float2* tab;
    cudaGetSymbolAddress((void**)&Xh,  g_Xh);
    cudaGetSymbolAddress((void**)&Xl,  g_Xl);
    cudaGetSymbolAddress((void**)&Wh,  g_Wh);
    cudaGetSymbolAddress((void**)&Wl,  g_Wl);
    cudaGetSymbolAddress((void**)&Qh,  g_Qh);
    cudaGetSymbolAddress((void**)&Ql,  g_Ql);
    cudaGetSymbolAddress((void**)&Khb, g_Kh);
    cudaGetSymbolAddress((void**)&Klb, g_Kl);
    cudaGetSymbolAddress((void**)&Vh,  g_Vh);
    cudaGetSymbolAddress((void**)&Vl,  g_Vl);
    cudaGetSymbolAddress((void**)&tab, g_tab);
    const size_t WSZ = (size_t)D_ * D_;

    const int M = B_ * S_;

    // one merged prep launch (weights + rope table + X split)
    prep_all<<<16384, 256>>>((const float4*)X, (const float4*)Wq, (const float4*)Wk,
                             (const float4*)Wv, (const float4*)Wo,
                             Xh, Xl, Wh, Wl, tab);

    cudaFuncSetAttribute(gemm_qkv, cudaFuncAttributeMaxDynamicSharedMemorySize, GEMM_SMEM);
    cudaFuncSetAttribute(gemm_out, cudaFuncAttributeMaxDynamicSharedMemorySize, GEMM_SMEM);

    gemm_qkv<<<dim3(D_ / BN, M / BM, 3), 256, GEMM_SMEM>>>(
        Xh, Xl, Wh, Wl, bq, bk, bv, Qh, Ql, Khb, Klb, Vh, Vl, tab);

    cudaFuncSetAttribute(attn_mma, cudaFuncAttributeMaxDynamicSharedMemorySize, ATTN_SMEM);
    attn_mma<<<dim3(S_ / 64, H_, B_), 128, ATTN_SMEM>>>(Qh, Ql, Khb, Klb, Vh, Vl, Xh, Xl);

    gemm_out<<<dim3(D_ / BN, M / BM), 256, GEMM_SMEM>>>(
        Xh, Xl, Wh + 3 * WSZ, Wl + 3 * WSZ, bo, out);
}

// round 17
// speedup vs baseline: 1.1373x; 1.0502x over previous
#include <cuda_runtime.h>
#include <cuda_bf16.h>
#include <cstdint>
#include <math.h>

#define B_  4
#define S_  2048
#define D_  1024
#define H_  16
#define HD_ 64

// ---------------------------------------------------------------------------
// Scratch (__device__ globals: allocation-free rule)
// ---------------------------------------------------------------------------
__device__ __nv_bfloat16 g_Xh[(size_t)B_ * S_ * D_];   // X hi, later attn-out hi
__device__ __nv_bfloat16 g_Xl[(size_t)B_ * S_ * D_];
__device__ __nv_bfloat16 g_Qh[(size_t)B_ * S_ * D_];
__device__ __nv_bfloat16 g_Ql[(size_t)B_ * S_ * D_];
__device__ __nv_bfloat16 g_Kh[(size_t)B_ * S_ * D_];
__device__ __nv_bfloat16 g_Kl[(size_t)B_ * S_ * D_];
__device__ __nv_bfloat16 g_Vh[(size_t)B_ * S_ * D_];
__device__ __nv_bfloat16 g_Vl[(size_t)B_ * S_ * D_];
__device__ __nv_bfloat16 g_Wh[4][(size_t)D_ * D_];
__device__ __nv_bfloat16 g_Wl[4][(size_t)D_ * D_];
__device__ float2 g_tab[(size_t)S_ * (D_ / 2)];

__device__ __forceinline__ uint32_t smem_u32(const void* p) {
    uint32_t a;
    asm("{ .reg .u64 t; cvta.to.shared.u64 t, %1; cvt.u32.u64 %0, t; }" : "=r"(a) : "l"(p));
    return a;
}
__device__ __forceinline__ void cp16(uint32_t s, const void* g) {
    asm volatile("cp.async.cg.shared.global [%0], [%1], 16;" :: "r"(s), "l"(g) : "memory");
}
#define LDSM_X4(r0, r1, r2, r3, a)                                              \
    asm volatile("ldmatrix.sync.aligned.m8n8.x4.shared.b16 {%0,%1,%2,%3}, [%4];" \
        : "=r"(r0), "=r"(r1), "=r"(r2), "=r"(r3) : "r"(a))
#define LDSM_X4T(r0, r1, r2, r3, a)                                                   \
    asm volatile("ldmatrix.sync.aligned.m8n8.x4.trans.shared.b16 {%0,%1,%2,%3}, [%4];" \
        : "=r"(r0), "=r"(r1), "=r"(r2), "=r"(r3) : "r"(a))

__device__ __forceinline__ void mma16816(float* d, const uint32_t* a, const uint32_t* b) {
    asm volatile(
        "mma.sync.aligned.m16n8k16.row.col.f32.bf16.bf16.f32 "
        "{%0,%1,%2,%3}, {%4,%5,%6,%7}, {%8,%9}, {%0,%1,%2,%3};"
        : "+f"(d[0]), "+f"(d[1]), "+f"(d[2]), "+f"(d[3])
        : "r"(a[0]), "r"(a[1]), "r"(a[2]), "r"(a[3]), "r"(b[0]), "r"(b[1]));
}

__device__ __forceinline__ uint32_t pack2(float lo, float hi) {
    uint32_t r;
    asm("cvt.rn.bf16x2.f32 %0, %1, %2;" : "=r"(r) : "f"(hi), "f"(lo));
    return r;
}
__device__ __forceinline__ uint32_t pack2_lo(uint32_t hp, float v0, float v1) {
    float r0 = v0 - __uint_as_float(hp << 16);
    float r1 = v1 - __uint_as_float(hp & 0xffff0000u);
    return pack2(r0, r1);
}

// ---------------------------------------------------------------------------
// Merged prep: weight splits (blocks 0..4095), rope table (4096..8191),
// X split (8192..16383).
// ---------------------------------------------------------------------------
__global__ void prep_all(const float4* __restrict__ X,
                         const float4* __restrict__ w0, const float4* __restrict__ w1,
                         const float4* __restrict__ w2, const float4* __restrict__ w3,
                         __nv_bfloat16* __restrict__ Xh, __nv_bfloat16* __restrict__ Xl,
                         __nv_bfloat16* __restrict__ Wh, __nv_bfloat16* __restrict__ Wl,
                         float2* __restrict__ tab)
{
    const int bid = blockIdx.x;
    const int tid = threadIdx.x;
    if (bid < 4096) {
        const int m = bid >> 10;
        const int i = ((bid & 1023) << 8) + tid;
        const float4* src = (m == 0) ? w0 : (m == 1) ? w1 : (m == 2) ? w2 : w3;
        const size_t off = (size_t)m * D_ * D_ + (size_t)i * 4;
        float4 x = src[i];
        uint2 h, l;
        h.x = pack2(x.x, x.y); l.x = pack2(x.x - __uint_as_float(h.x << 16),
                                           x.y - __uint_as_float(h.x & 0xffff0000u));
        h.y = pack2(x.z, x.w); l.y = pack2(x.z - __uint_as_float(h.y << 16),
                                           x.w - __uint_as_float(h.y & 0xffff0000u));
        *(uint2*)&Wh[off] = h;
        *(uint2*)&Wl[off] = l;
    } else if (bid < 8192) {
        const int idx = ((bid - 4096) << 8) + tid;
        const int p = idx & (D_ / 2 - 1);
        const int s = idx >> 9;
        const float inv = exp2f((float)p * (-13.287712379549449f / (float)(D_ / 2)));
        float sn, c;
        sincosf((float)s * inv, &sn, &c);
        tab[idx] = make_float2(c, sn);
    } else {
        const int i = ((bid - 8192) << 8) + tid;
        float4 x = X[i];
        uint2 h, l;
        h.x = pack2(x.x, x.y); l.x = pack2(x.x - __uint_as_float(h.x << 16),
                                           x.y - __uint_as_float(h.x & 0xffff0000u));
        h.y = pack2(x.z, x.w); l.y = pack2(x.z - __uint_as_float(h.y << 16),
                                           x.w - __uint_as_float(h.y & 0xffff0000u));
        *(uint2*)&Xh[(size_t)i * 4] = h;
        *(uint2*)&Xl[(size_t)i * 4] = l;
    }
}

// ---------------------------------------------------------------------------
// GEMM tiles / pipeline constants
// ---------------------------------------------------------------------------
#define BM 128
#define BN 128
#define BK 32
#define APITCH 40
#define BPITCH 136
#define A_BYTES (BM * APITCH * 2)
#define B_BYTES (BK * BPITCH * 2)
#define STG     (2 * A_BYTES + 2 * B_BYTES)   // 37888
#define NSTAGE  3
#define GEMM_SMEM (NSTAGE * STG)              // 113664

// Mainloop: single sync/chunk; next-stage cp.async issued BETWEEN ks0 and ks1.
#define GEMM_MAINLOOP(Ah, Al, Bh, Bl)                                                     \
    auto load_stage = [&](int s, int k0) {                                                \
        const uint32_t sbst = sbase + (uint32_t)s * STG;                                  \
        _Pragma("unroll")                                                                 \
        for (int it = 0; it < 2; it++) {                                                  \
            const int idx = it * 256 + t;                                                 \
            const int m   = idx >> 2;                                                     \
            const int ca  = idx & 3;                                                      \
            const size_t ga = (size_t)(row0 + m) * 1024 + k0 + ca * 8;                    \
            const uint32_t soa = (uint32_t)(m * APITCH * 2 + ca * 16);                    \
            cp16(sbst + soa,           Ah + ga);                                          \
            cp16(sbst + A_BYTES + soa, Al + ga);                                          \
            const int kr = idx >> 4;                                                      \
            const int cb = idx & 15;                                                      \
            const size_t gb = (size_t)(k0 + kr) * 1024 + col0 + cb * 8;                   \
            const uint32_t sob = (uint32_t)(kr * BPITCH * 2 + cb * 16);                   \
            cp16(sbst + 2 * A_BYTES + sob,           Bh + gb);                            \
            cp16(sbst + 2 * A_BYTES + B_BYTES + sob, Bl + gb);                            \
        }                                                                                 \
        asm volatile("cp.async.commit_group;" ::: "memory");                              \
    };                                                                                    \
    const int NCH = 1024 / BK;                                                            \
    load_stage(0, 0);                                                                     \
    load_stage(1, BK);                                                                    \
    for (int ch = 0; ch < NCH; ch++) {                                                    \
        if (ch + 1 < NCH) asm volatile("cp.async.wait_group 1;" ::: "memory");            \
        else              asm volatile("cp.async.wait_group 0;" ::: "memory");            \
        __syncthreads();                                                                  \
        const uint32_t sb  = sbase + (uint32_t)(ch % NSTAGE) * STG;                       \
        const uint32_t aAh = sb;                                                          \
        const uint32_t aAl = sb + A_BYTES;                                                \
        const uint32_t aBh = sb + 2 * A_BYTES;                                            \
        const uint32_t aBl = aBh + B_BYTES;                                               \
        _Pragma("unroll")                                                                 \
        for (int ks = 0; ks < 2; ks++) {                                                  \
            uint32_t bh[4][2], bl[4][2];                                                  \
            const int kr = ks * 16 + (lane & 15);                                         \
            const int nc = wn * 32 + (lane >> 4) * 8;                                     \
            _Pragma("unroll")                                                             \
            for (int jp = 0; jp < 2; jp++) {                                              \
                const uint32_t off = (uint32_t)((kr * BPITCH + nc + jp * 16) * 2);        \
                LDSM_X4T(bh[2*jp][0], bh[2*jp][1], bh[2*jp+1][0], bh[2*jp+1][1], aBh+off);\
                LDSM_X4T(bl[2*jp][0], bl[2*jp][1], bl[2*jp+1][0], bl[2*jp+1][1], aBl+off);\
            }                                                                             \
            uint32_t ah2[2][4], al2[2][4];                                                \
            const int mr = wm * 64 + (lane & 15);                                         \
            const int kc = ks * 16 + (lane >> 4) * 8;                                     \
            {                                                                             \
                const uint32_t off = (uint32_t)((mr * APITCH + kc) * 2);                  \
                LDSM_X4(ah2[0][0], ah2[0][1], ah2[0][2], ah2[0][3], aAh + off);           \
                LDSM_X4(al2[0][0], al2[0][1], al2[0][2], al2[0][3], aAl + off);           \
            }                                                                             \
            _Pragma("unroll")                                                             \
            for (int i = 0; i < 4; i++) {                                                 \
                if (i < 3) {                                                              \
                    const uint32_t off = (uint32_t)(((mr + (i+1)*16) * APITCH + kc) * 2); \
                    LDSM_X4(ah2[(i+1)&1][0], ah2[(i+1)&1][1],                             \
                            ah2[(i+1)&1][2], ah2[(i+1)&1][3], aAh + off);                 \
                    LDSM_X4(al2[(i+1)&1][0], al2[(i+1)&1][1],                             \
                            al2[(i+1)&1][2], al2[(i+1)&1][3], aAl + off);                 \
                }                                                                         \
                _Pragma("unroll")                                                         \
                for (int j = 0; j < 4; j++) mma16816(acc[i][j], ah2[i&1], bh[j]);         \
                _Pragma("unroll")                                                         \
                for (int j = 0; j < 4; j++) mma16816(acc[i][j], ah2[i&1], bl[j]);         \
                _Pragma("unroll")                                                         \
                for (int j = 0; j < 4; j++) mma16816(acc[i][j], al2[i&1], bh[j]);         \
            }                                                                             \
            if (ks == 0 && ch + 2 < NCH) load_stage((ch + 2) % NSTAGE, (ch + 2) * BK);    \
        }                                                                                 \
    }

// ---------------------------------------------------------------------------
// Fused Q/K/V projection GEMM (2 CTAs/SM forced: regs capped at 128)
// ---------------------------------------------------------------------------
__global__ __launch_bounds__(256, 2)
void gemm_qkv(const __nv_bfloat16* __restrict__ Ah, const __nv_bfloat16* __restrict__ Al,
              const __nv_bfloat16* __restrict__ Whb, const __nv_bfloat16* __restrict__ Wlb,
              const float* __restrict__ bq, const float* __restrict__ bk,
              const float* __restrict__ bv,
              __nv_bfloat16* __restrict__ Qh, __nv_bfloat16* __restrict__ Ql,
              __nv_bfloat16* __restrict__ Kh, __nv_bfloat16* __restrict__ Kl,
              __nv_bfloat16* __restrict__ Vh, __nv_bfloat16* __restrict__ Vl,
              const float2* __restrict__ tab)
{
    extern __shared__ char smraw[];
    const uint32_t sbase = smem_u32(smraw);
    const int t    = threadIdx.x;
    const int lane = t & 31;
    const int wid  = t >> 5;
    const int wm   = wid & 1;
    const int wn   = wid >> 1;
    const int row0 = blockIdx.y * BM;
    const int col0 = blockIdx.x * BN;
    const int z    = blockIdx.z;

    const size_t WSZ = (size_t)D_ * D_;
    const __nv_bfloat16* Bh = Whb + (size_t)z * WSZ;
    const __nv_bfloat16* Bl = Wlb + (size_t)z * WSZ;
    const float* bias = (z == 0) ? bq : (z == 1) ? bk : bv;
    __nv_bfloat16* Oh = (z == 0) ? Qh : (z == 1) ? Kh : Vh;
    __nv_bfloat16* Ol = (z == 0) ? Ql : (z == 1) ? Kl : Vl;

    float acc[4][4][4];
    #pragma unroll
    for (int i = 0; i < 4; i++)
        #pragma unroll
        for (int j = 0; j < 4; j++)
            #pragma unroll
            for (int v = 0; v < 4; v++) acc[i][j][v] = 0.f;

    GEMM_MAINLOOP(Ah, Al, Bh, Bl)

    const int gr = lane >> 2;
    const int gc = (lane & 3) * 2;
    const bool do_rope = (z < 2);
    #pragma unroll
    for (int i = 0; i < 4; i++) {
        const int r0g = row0 + wm * 64 + i * 16 + gr;
        const int r1g = r0g + 8;
        #pragma unroll
        for (int j = 0; j < 4; j++) {
            const int c = col0 + wn * 32 + j * 8 + gc;
            const float b0 = bias[c], b1 = bias[c + 1];
            float v00 = acc[i][j][0] + b0, v01 = acc[i][j][1] + b1;
            float v10 = acc[i][j][2] + b0, v11 = acc[i][j][3] + b1;
            if (do_rope) {
                const int p = c >> 1;
                const float2 cs0 = tab[(size_t)(r0g & (S_ - 1)) * (D_ / 2) + p];
                const float2 cs1 = tab[(size_t)(r1g & (S_ - 1)) * (D_ / 2) + p];
                float t0 = v00 * cs0.x - v01 * cs0.y;
                float t1 = v00 * cs0.y + v01 * cs0.x;
                v00 = t0; v01 = t1;
                t0 = v10 * cs1.x - v11 * cs1.y;
                t1 = v10 * cs1.y + v11 * cs1.x;
                v10 = t0; v11 = t1;
            }
            const size_t a0 = (size_t)r0g * D_ + c;
            const size_t a1 = (size_t)r1g * D_ + c;
            const uint32_t h0 = pack2(v00, v01);
            const uint32_t h1 = pack2(v10, v11);
            *(uint32_t*)&Oh[a0] = h0;
            *(uint32_t*)&Ol[a0] = pack2_lo(h0, v00, v01);
            *(uint32_t*)&Oh[a1] = h1;
            *(uint32_t*)&Ol[a1] = pack2_lo(h1, v10, v11);
        }
    }
}

// ---------------------------------------------------------------------------
// Output projection GEMM (fp32 epilogue; 2 CTAs/SM forced)
// ---------------------------------------------------------------------------
__global__ __launch_bounds__(256, 2)
void gemm_out(const __nv_bfloat16* __restrict__ Ah, const __nv_bfloat16* __restrict__ Al,
              const __nv_bfloat16* __restrict__ Bh, const __nv_bfloat16* __restrict__ Bl,
              const float* __restrict__ bias, float* __restrict__ C)
{
    extern __shared__ char smraw[];
    const uint32_t sbase = smem_u32(smraw);
    const int t    = threadIdx.x;
    const int lane = t & 31;
    const int wid  = t >> 5;
    const int wm   = wid & 1;
    const int wn   = wid >> 1;
    const int row0 = blockIdx.y * BM;
    const int col0 = blockIdx.x * BN;

    float acc[4][4][4];
    #pragma unroll
    for (int i = 0; i < 4; i++)
        #pragma unroll
        for (int j = 0; j < 4; j++)
            #pragma unroll
            for (int v = 0; v < 4; v++) acc[i][j][v] = 0.f;

    GEMM_MAINLOOP(Ah, Al, Bh, Bl)

    const int gr = lane >> 2;
    const int gc = (lane & 3) * 2;
    #pragma unroll
    for (int i = 0; i < 4; i++) {
        const int r0g = row0 + wm * 64 + i * 16 + gr;
        const int r1g = r0g + 8;
        #pragma unroll
        for (int j = 0; j < 4; j++) {
            const int c = col0 + wn * 32 + j * 8 + gc;
            const float b0 = bias[c], b1 = bias[c + 1];
            *(float2*)&C[(size_t)r0g * D_ + c] =
                make_float2(acc[i][j][0] + b0, acc[i][j][1] + b1);
            *(float2*)&C[(size_t)r1g * D_ + c] =
                make_float2(acc[i][j][2] + b0, acc[i][j][3] + b1);
        }
    }
}

// ---------------------------------------------------------------------------
// Tensor-core causal flash attention, bf16x3 — R11/R14 version (frozen).
// ---------------------------------------------------------------------------
#define KROW_B 144
#define TILE_B (64 * KROW_B)
#define ASTG   (4 * TILE_B)
#define ATTN_SMEM (2 * ASTG)

__global__ __launch_bounds__(128, 3)
void attn_mma(const __nv_bfloat16* __restrict__ Qh, const __nv_bfloat16* __restrict__ Ql,
              const __nv_bfloat16* __restrict__ Kh, const __nv_bfloat16* __restrict__ Kl,
              const __nv_bfloat16* __restrict__ Vh, const __nv_bfloat16* __restrict__ Vl,
              __nv_bfloat16* __restrict__ Oh, __nv_bfloat16* __restrict__ Ol)
{
    extern __shared__ char smraw[];
    const uint32_t sb0 = smem_u32(smraw);
    const int t = threadIdx.x, lane = t & 31, w = t >> 5;
    const int qb = gridDim.x - 1 - blockIdx.x;
    const int h = blockIdx.y, b = blockIdx.z;
    const size_t bh = (size_t)b * S_ * D_ + (size_t)h * HD_;
    const int q0 = qb * 64;

    auto load_kv = [&](int kb) {
        const uint32_t sb = sb0 + (uint32_t)(kb & 1) * ASTG;
        #pragma unroll
        for (int it = 0; it < 4; it++) {
            const int idx = it * 128 + t;
            const int r = idx >> 3, c = idx & 7;
            const size_t g = bh + (size_t)(kb * 64 + r) * D_ + c * 8;
            const uint32_t so = (uint32_t)(r * KROW_B + c * 16);
            cp16(sb + so,              Kh + g);
            cp16(sb + TILE_B + so,     Kl + g);
            cp16(sb + 2 * TILE_B + so, Vh + g);
            cp16(sb + 3 * TILE_B + so, Vl + g);
        }
        asm volatile("cp.async.commit_group;" ::: "memory");
    };

    const uint32_t qbuf = sb0 + ASTG;
    #pragma unroll
    for (int it = 0; it < 4; it++) {
        const int idx = it * 128 + t;
        const int r = idx >> 3, c = idx & 7;
        const size_t g = bh + (size_t)(q0 + r) * D_ + c * 8;
        const uint32_t so = (uint32_t)(r * KROW_B + c * 16);
        cp16(qbuf + so,          Qh + g);
        cp16(qbuf + TILE_B + so, Ql + g);
    }
    asm volatile("cp.async.commit_group;" ::: "memory");
    load_kv(0);
    asm volatile("cp.async.wait_group 1;" ::: "memory");
    __syncthreads();

    uint32_t qhf[4][4], qlf[4][4];
    {
        const int mr = w * 16 + (lane & 15);
        #pragma unroll
        for (int ks = 0; ks < 4; ks++) {
            const uint32_t off = (uint32_t)(mr * KROW_B + ks * 32 + (lane >> 4) * 16);
            LDSM_X4(qhf[ks][0], qhf[ks][1], qhf[ks][2], qhf[ks][3], qbuf + off);
            LDSM_X4(qlf[ks][0], qlf[ks][1], qlf[ks][2], qlf[ks][3], qbuf + TILE_B + off);
        }
    }
    __syncthreads();

    const int gr  = lane >> 2;
    const int gc2 = (lane & 3) * 2;
    const int row0g = q0 + w * 16 + gr;
    const int row1g = row0g + 8;

    float m0 = -1e30f, m1 = -1e30f, l0 = 0.f, l1 = 0.f;
    float oa[8][4];
    #pragma unroll
    for (int nf = 0; nf < 8; nf++)
        #pragma unroll
        for (int v = 0; v < 4; v++) oa[nf][v] = 0.f;

    for (int kb = 0; kb <= qb; kb++) {
        asm volatile("cp.async.wait_group 0;" ::: "memory");
        __syncthreads();
        if (kb < qb) load_kv(kb + 1);
        const uint32_t sb = sb0 + (uint32_t)(kb & 1) * ASTG;

        float sa[8][4];
        #pragma unroll
        for (int nf = 0; nf < 8; nf++)
            #pragma unroll
            for (int v = 0; v < 4; v++) sa[nf][v] = 0.f;

        #pragma unroll
        for (int ks = 0; ks < 4; ks++) {
            uint32_t kbh[8][2], kbl[8][2];
            #pragma unroll
            for (int nf16 = 0; nf16 < 4; nf16++) {
                const uint32_t off = (uint32_t)((nf16 * 16 + (lane & 15)) * KROW_B
                                                + ks * 32 + (lane >> 4) * 16);
                uint32_t r0, r1, r2, r3;
                LDSM_X4(r0, r1, r2, r3, sb + off);
                kbh[2 * nf16][0] = r0; kbh[2 * nf16][1] = r2;
                kbh[2 * nf16 + 1][0] = r1; kbh[2 * nf16 + 1][1] = r3;
                LDSM_X4(r0, r1, r2, r3, sb + TILE_B + off);
                kbl[2 * nf16][0] = r0; kbl[2 * nf16][1] = r2;
                kbl[2 * nf16 + 1][0] = r1; kbl[2 * nf16 + 1][1] = r3;
            }
            #pragma unroll
            for (int nf = 0; nf < 8; nf++) {
                mma16816(sa[nf], qhf[ks], kbh[nf]);
                mma16816(sa[nf], qhf[ks], kbl[nf]);
                mma16816(sa[nf], qlf[ks], kbh[nf]);
            }
        }

        #pragma unroll
        for (int nf = 0; nf < 8; nf++)
            #pragma unroll
            for (int v = 0; v < 4; v++) sa[nf][v] *= 0.125f;

        if (kb == qb) {
            #pragma unroll
            for (int nf = 0; nf < 8; nf++) {
                const int col = kb * 64 + nf * 8 + gc2;
                if (col     > row0g) sa[nf][0] = -1e30f;
                if (col + 1 > row0g) sa[nf][1] = -1e30f;
                if (col     > row1g) sa[nf][2] = -1e30f;
                if (col + 1 > row1g) sa[nf][3] = -1e30f;
            }
        }

        float mt0 = sa[0][0], mt1 = sa[0][2];
        #pragma unroll
        for (int nf = 0; nf < 8; nf++) {
            mt0 = fmaxf(mt0, fmaxf(sa[nf][0], sa[nf][1]));
            mt1 = fmaxf(mt1, fmaxf(sa[nf][2], sa[nf][3]));
        }
        mt0 = fmaxf(mt0, __shfl_xor_sync(0xffffffffu, mt0, 1));
        mt0 = fmaxf(mt0, __shfl_xor_sync(0xffffffffu, mt0, 2));
        mt1 = fmaxf(mt1, __shfl_xor_sync(0xffffffffu, mt1, 1));
        mt1 = fmaxf(mt1, __shfl_xor_sync(0xffffffffu, mt1, 2));

        const float mn0 = fmaxf(m0, mt0), mn1 = fmaxf(m1, mt1);
        const float c0 = __expf(m0 - mn0), c1 = __expf(m1 - mn1);
        float s0 = 0.f, s1 = 0.f;
        #pragma unroll
        for (int nf = 0; nf < 8; nf++) {
            sa[nf][0] = __expf(sa[nf][0] - mn0); s0 += sa[nf][0];
            sa[nf][1] = __expf(sa[nf][1] - mn0); s0 += sa[nf][1];
            sa[nf][2] = __expf(sa[nf][2] - mn1); s1 += sa[nf][2];
            sa[nf][3] = __expf(sa[nf][3] - mn1); s1 += sa[nf][3];
        }
        s0 += __shfl_xor_sync(0xffffffffu, s0, 1);
        s0 += __shfl_xor_sync(0xffffffffu, s0, 2);
        s1 += __shfl_xor_sync(0xffffffffu, s1, 1);
        s1 += __shfl_xor_sync(0xffffffffu, s1, 2);
        l0 = l0 * c0 + s0;  l1 = l1 * c1 + s1;
        m0 = mn0;           m1 = mn1;

        #pragma unroll
        for (int nf = 0; nf < 8; nf++) {
            oa[nf][0] *= c0; oa[nf][1] *= c0;
            oa[nf][2] *= c1; oa[nf][3] *= c1;
        }

        #pragma unroll
        for (int ks = 0; ks < 4; ks++) {
            uint32_t ph[4], pl[4];
            ph[0] = pack2(sa[2 * ks][0],     sa[2 * ks][1]);
            pl[0] = pack2_lo(ph[0], sa[2 * ks][0], sa[2 * ks][1]);
            ph[1] = pack2(sa[2 * ks][2],     sa[2 * ks][3]);
            pl[1] = pack2_lo(ph[1], sa[2 * ks][2], sa[2 * ks][3]);
            ph[2] = pack2(sa[2 * ks + 1][0], sa[2 * ks + 1][1]);
            pl[2] = pack2_lo(ph[2], sa[2 * ks + 1][0], sa[2 * ks + 1][1]);
            ph[3] = pack2(sa[2 * ks + 1][2], sa[2 * ks + 1][3]);
            pl[3] = pack2_lo(ph[3], sa[2 * ks + 1][2], sa[2 * ks + 1][3]);

            uint32_t vbh[8][2], vbl[8][2];
            #pragma unroll
            for (int nf16 = 0; nf16 < 4; nf16++) {
                const uint32_t off = (uint32_t)((ks * 16 + (lane & 15)) * KROW_B
                                                + nf16 * 32 + (lane >> 4) * 16);
                LDSM_X4T(vbh[2 * nf16][0], vbh[2 * nf16][1],
                         vbh[2 * nf16 + 1][0], vbh[2 * nf16 + 1][1], sb + 2 * TILE_B + off);
                LDSM_X4T(vbl[2 * nf16][0], vbl[2 * nf16][1],
                         vbl[2 * nf16 + 1][0], vbl[2 * nf16 + 1][1], sb + 3 * TILE_B + off);
            }
            #pragma unroll
            for (int nf = 0; nf < 8; nf++) {
                mma16816(oa[nf], ph, vbh[nf]);
                mma16816(oa[nf], ph, vbl[nf]);
                mma16816(oa[nf], pl, vbh[nf]);
            }
        }
    }

    const float iv0 = 1.f / l0, iv1 = 1.f / l1;
    #pragma unroll
    for (int nf = 0; nf < 8; nf++) {
        const size_t a0 = bh + (size_t)(q0 + w * 16 + gr) * D_ + nf * 8 + gc2;
        const size_t a1 = a0 + 8 * D_;
        const float o00 = oa[nf][0] * iv0, o01 = oa[nf][1] * iv0;
        const float o10 = oa[nf][2] * iv1, o11 = oa[nf][3] * iv1;
        const uint32_t hp0 = pack2(o00, o01);
        const uint32_t hp1 = pack2(o10, o11);
        *(uint32_t*)&Oh[a0] = hp0;
        *(uint32_t*)&Ol[a0] = pack2_lo(hp0, o00, o01);
        *(uint32_t*)&Oh[a1] = hp1;
        *(uint32_t*)&Ol[a1] = pack2_lo(hp1, o10, o11);
    }
}

// ---------------------------------------------------------------------------
extern "C" void kernel_launch(void* const* d_in, const int* in_sizes, int n_in,
                              void* d_out, int out_size)
{
    const float* X  = (const float*)d_in[0];
    const float* Wq = (const float*)d_in[1];
    const float* bq = (const float*)d_in[2];
    const float* Wk = (const float*)d_in[3];
    const float* bk = (const float*)d_in[4];
    const float* Wv = (const float*)d_in[5];
    const float* bv = (const float*)d_in[6];
    const float* Wo = (const float*)d_in[7];
    const float* bo = (const float*)d_in[8];
    float* out = (float*)d_out;

    __nv_bfloat16 *Xh, *Xl, *Wh, *Wl, *Qh, *Ql, *Khb, *Klb, *Vh, *Vl;
    float2* tab;
    cudaGetSymbolAddress((void**)&Xh,  g_Xh);
    cudaGetSymbolAddress((void**)&Xl,  g_Xl);
    cudaGetSymbolAddress((void**)&Wh,  g_Wh);
    cudaGetSymbolAddress((void**)&Wl,  g_Wl);
    cudaGetSymbolAddress((void**)&Qh,  g_Qh);
    cudaGetSymbolAddress((void**)&Ql,  g_Ql);
    cudaGetSymbolAddress((void**)&Khb, g_Kh);
    cudaGetSymbolAddress((void**)&Klb, g_Kl);
    cudaGetSymbolAddress((void**)&Vh,  g_Vh);
    cudaGetSymbolAddress((void**)&Vl,  g_Vl);
    cudaGetSymbolAddress((void**)&tab, g_tab);
    const size_t WSZ = (size_t)D_ * D_;

    const int M = B_ * S_;

    prep_all<<<16384, 256>>>((const float4*)X, (const float4*)Wq, (const float4*)Wk,
                             (const float4*)Wv, (const float4*)Wo,
                             Xh, Xl, Wh, Wl, tab);

    cudaFuncSetAttribute(gemm_qkv, cudaFuncAttributeMaxDynamicSharedMemorySize, GEMM_SMEM);
    cudaFuncSetAttribute(gemm_out, cudaFuncAttributeMaxDynamicSharedMemorySize, GEMM_SMEM);

    gemm_qkv<<<dim3(D_ / BN, M / BM, 3), 256, GEMM_SMEM>>>(
        Xh, Xl, Wh, Wl, bq, bk, bv, Qh, Ql, Khb, Klb, Vh, Vl, tab);

    cudaFuncSetAttribute(attn_mma, cudaFuncAttributeMaxDynamicSharedMemorySize, ATTN_SMEM);
    attn_mma<<<dim3(S_ / 64, H_, B_), 128, ATTN_SMEM>>>(Qh, Ql, Khb, Klb, Vh, Vl, Xh, Xl);

    gemm_out<<<dim3(D_ / BN, M / BM), 256, GEMM_SMEM>>>(
        Xh, Xl, Wh + 3 * WSZ, Wl + 3 * WSZ, bo, out);
}